// round 13
// baseline (speedup 1.0000x reference)
#include <cuda_runtime.h>
#include <cuda_fp16.h>

typedef unsigned int u32;
typedef unsigned long long u64;

#define NB 64
#define CIN 128
#define COUT 128
#define TT 128
#define JJ 25

#define TSLAB 16
#define CHT 2
#define NCHUNK 8
#define NTILES 7
#define AP 136
#define BP 56
#define RAWP 51
#define XP 40

// ---- smem byte offsets (round-10 layout) ----
#define SM_CSF   0
#define SM_SBN   128
#define SM_E16H  2176
#define SM_E16L  4736
#define SM_A_HI  7296
#define SM_A_LO  42112
#define SM_B0    76928
#define B_HALF   14336
#define B_BUF    28672
#define SM_BH(b) (SM_B0 + (b)*B_BUF)
#define SM_BL(b) (SM_BH(b) + B_HALF)
#define SM_X_HI  134272
#define SM_X_LO  154752
#define SM_RAW0  175232
#define RAW_BYTES 26112
#define SM_RAW(b) (SM_RAW0 + (b)*RAW_BYTES)
#define SMEM_TOTAL 227456

// prologue scratch inside B region (dead before pipeline starts)
#define P_XT  SM_B0              // 128x26 f32 = 13312
#define P_KK  (SM_B0 + 13312)
#define P_QQ  (SM_B0 + 26624)
#define P_SD  (SM_B0 + 39936)    // 25x26 f32 = 2600

// named barrier ids
#define BAR_FULL(b) (1 + (b))
#define BAR_FREE(b) (3 + (b))
#define BAR_PROD    5
#define BAR_CONS    6

// ---------------- scratch ----------------
__device__ float g_xt_mean[NB * CIN * JJ];

// ---------------- helpers ----------------
__device__ __forceinline__ u32 smem_u32(const void* p) {
    u32 a; asm("{ .reg .u64 t; cvta.to.shared.u64 t, %1; cvt.u32.u64 %0, t; }" : "=r"(a) : "l"(p));
    return a;
}
__device__ __forceinline__ void ldsm_x4(u32* r, u32 addr) {
    asm volatile("ldmatrix.sync.aligned.m8n8.x4.shared.b16 {%0,%1,%2,%3}, [%4];"
        : "=r"(r[0]), "=r"(r[1]), "=r"(r[2]), "=r"(r[3]) : "r"(addr) : "memory");
}
__device__ __forceinline__ void ldsm_x4t(u32* r, u32 addr) {
    asm volatile("ldmatrix.sync.aligned.m8n8.x4.trans.shared.b16 {%0,%1,%2,%3}, [%4];"
        : "=r"(r[0]), "=r"(r[1]), "=r"(r[2]), "=r"(r[3]) : "r"(addr) : "memory");
}
__device__ __forceinline__ void ldsm_x2t(u32* r, u32 addr) {
    asm volatile("ldmatrix.sync.aligned.m8n8.x2.trans.shared.b16 {%0,%1}, [%2];"
        : "=r"(r[0]), "=r"(r[1]) : "r"(addr) : "memory");
}
__device__ __forceinline__ void mma_fp16(float* d, const u32* a, const u32* b) {
    asm volatile("mma.sync.aligned.m16n8k16.row.col.f32.f16.f16.f32 "
        "{%0,%1,%2,%3}, {%4,%5,%6,%7}, {%8,%9}, {%0,%1,%2,%3};"
        : "+f"(d[0]), "+f"(d[1]), "+f"(d[2]), "+f"(d[3])
        : "r"(a[0]), "r"(a[1]), "r"(a[2]), "r"(a[3]), "r"(b[0]), "r"(b[1]));
}
__device__ __forceinline__ void cp4(u32 dst, const void* src) {
    asm volatile("cp.async.ca.shared.global [%0], [%1], 4;" :: "r"(dst), "l"(src) : "memory");
}
#define CP_COMMIT() asm volatile("cp.async.commit_group;" ::: "memory")
#define CP_WAIT1()  asm volatile("cp.async.wait_group 1;" ::: "memory")
#define CP_WAITALL() asm volatile("cp.async.wait_group 0;" ::: "memory")
#define BAR_SYNC(id, cnt) asm volatile("bar.sync %0, %1;" :: "r"(id), "r"(cnt) : "memory")
#define BAR_ARRIVE(id, cnt) asm volatile("bar.arrive %0, %1;" :: "r"(id), "r"(cnt) : "memory")

__device__ __forceinline__ u32 packh(float a, float b) {
    __half h0 = __float2half_rn(a), h1 = __float2half_rn(b);
    return (u32)__half_as_ushort(h0) | ((u32)__half_as_ushort(h1) << 16);
}

// ---------------- K1: temporal mean (2 channels / warp for MLP) ----------------
__global__ void k1_mean(const float* __restrict__ x) {
    int b = blockIdx.y;
    int c0 = blockIdx.x * 16 + (threadIdx.x >> 5) * 2;
    int j = threadIdx.x & 31;
    if (j >= JJ) return;
    const float* p0 = x + ((size_t)(b * CIN + c0) * TT) * JJ + j;
    const float* p1 = p0 + (size_t)TT * JJ;
    float a0 = 0.f, a1 = 0.f, a2 = 0.f, a3 = 0.f;
    float b0 = 0.f, b1 = 0.f, b2 = 0.f, b3 = 0.f;
#pragma unroll 8
    for (int t = 0; t < TT; t += 4) {
        a0 += p0[t * JJ];       b0 += p1[t * JJ];
        a1 += p0[(t + 1) * JJ]; b1 += p1[(t + 1) * JJ];
        a2 += p0[(t + 2) * JJ]; b2 += p1[(t + 2) * JJ];
        a3 += p0[(t + 3) * JJ]; b3 += p1[(t + 3) * JJ];
    }
    g_xt_mean[(b * CIN + c0) * JJ + j]     = ((a0 + a1) + (a2 + a3)) * (1.0f / TT);
    g_xt_mean[(b * CIN + c0 + 1) * JJ + j] = ((b0 + b1) + (b2 + b3)) * (1.0f / TT);
}

// ---------------- K3: fused attention prologue + warp-specialized GEMM ----------------
__global__ void __launch_bounds__(512, 1)
k3_main(const float* __restrict__ x, const float* __restrict__ Ws,
        const float* __restrict__ bs, const float* __restrict__ gamma,
        const float* __restrict__ beta, const float* __restrict__ rmean,
        const float* __restrict__ rvar, float* __restrict__ out,
        const float* __restrict__ adj, const float* __restrict__ Wk,
        const float* __restrict__ bk, const float* __restrict__ Wq,
        const float* __restrict__ bq, const float* __restrict__ alphaPtr) {
    extern __shared__ char sm[];
    u32 sbase = smem_u32(sm);
    int tid = threadIdx.x;
    int b = blockIdx.y, slab = blockIdx.x;
    int t0slab = slab * TSLAB;

    bool is_prod = tid >= 256;
    int ptid = tid & 255;
    const float* xb = x + (size_t)b * 409600 + (size_t)t0slab * 25;

    // ---- producers: cp.async raw chunks 0,1 (land during prologue) ----
    if (is_prod) {
#pragma unroll
        for (int cb = 0; cb < 2; ++cb) {
#pragma unroll
            for (int k = 0; k < 25; ++k) {
                int flat = ptid + 256 * k;
                int c = flat / 50, col = flat - 50 * c;
                cp4(sbase + SM_RAW(cb) + (u32)((c * RAWP + col) * 4),
                    xb + (size_t)c * 3200 + cb * 50 + col);
            }
            CP_COMMIT();
        }
    }

    // ---- staging: SBN, A, xt ----
    if (tid < 128) {
        int o = tid;
        float inv = gamma[o] * rsqrtf(rvar[o] + 1e-5f);
        float sh = beta[o] - rmean[o] * inv;
        ((float4*)(sm + SM_SBN))[o] = make_float4(inv, sh, bs[o], 0.f);
    }
    {
        __half* ah = (__half*)(sm + SM_A_HI);
        __half* al = (__half*)(sm + SM_A_LO);
        for (int i = tid; i < COUT * CIN; i += 512) {
            int o = i >> 7, c = i & 127;
            float v = Ws[i];
            __half hb = __float2half_rn(v);
            ah[o * AP + c] = hb;
            al[o * AP + c] = __float2half_rn(v - __half2float(hb));
        }
    }
    {
        float* xt = (float*)(sm + P_XT);
        for (int i = tid; i < CIN * JJ; i += 512) {
            int c = i / JJ, j = i - c * JJ;
            xt[c * 26 + j] = g_xt_mean[b * CIN * JJ + i];
        }
    }
    __syncthreads();

    // ======== fused k2 prologue: compute E16 hi/lo + csf in-CTA ========
    float alpha = alphaPtr[0];
    {
        const float* xt = (const float*)(sm + P_XT);
        float* kk = (float*)(sm + P_KK);
        float* qq = (float*)(sm + P_QQ);
        int o = tid >> 2, part = tid & 3;
        int j0 = part * 7;
        int nj = (part == 3) ? 4 : 7;
        const float4* wk4 = (const float4*)(Wk + o * CIN);
        const float4* wq4 = (const float4*)(Wq + o * CIN);
        float ak[7], aq[7];
#pragma unroll
        for (int jj = 0; jj < 7; ++jj) { ak[jj] = 0.f; aq[jj] = 0.f; }
#pragma unroll 4
        for (int c4 = 0; c4 < CIN / 4; ++c4) {
            float4 wk = wk4[c4], wq = wq4[c4];
            const float* x0 = xt + (c4 * 4) * 26 + j0;
#pragma unroll
            for (int jj = 0; jj < 7; ++jj) {
                if (jj < nj) {
                    float v0 = x0[jj], v1 = x0[26 + jj], v2 = x0[52 + jj], v3 = x0[78 + jj];
                    float a = ak[jj], q = aq[jj];
                    a = fmaf(wk.x, v0, a); q = fmaf(wq.x, v0, q);
                    a = fmaf(wk.y, v1, a); q = fmaf(wq.y, v1, q);
                    a = fmaf(wk.z, v2, a); q = fmaf(wq.z, v2, q);
                    a = fmaf(wk.w, v3, a); q = fmaf(wq.w, v3, q);
                    ak[jj] = a; aq[jj] = q;
                }
            }
        }
        float bko = bk[o], bqo = bq[o];
#pragma unroll
        for (int jj = 0; jj < 7; ++jj)
            if (jj < nj) {
                kk[o * 26 + j0 + jj] = ak[jj] + bko;
                qq[o * 26 + j0 + jj] = aq[jj] + bqo;
            }
    }
    __syncthreads();
    {   // scores
        const float* kk = (const float*)(sm + P_KK);
        const float* qq = (const float*)(sm + P_QQ);
        float* sdyn = (float*)(sm + P_SD);
        const float inv_scale = 0.08838834764831843f;  // 1/sqrt(128)
        for (int i = tid; i < JJ * JJ; i += 512) {
            int j = i / JJ, k = i - j * JJ;
            float acc = 0.f;
            for (int o = 0; o < COUT; o++) acc = fmaf(qq[o * 26 + j], kk[o * 26 + k], acc);
            sdyn[j * 26 + k] = acc * inv_scale;
        }
    }
    __syncthreads();
    if (tid < JJ) {   // row softmax
        float* sdyn = (float*)(sm + P_SD);
        int j = tid;
        float m = -1e30f;
#pragma unroll
        for (int k = 0; k < JJ; k++) m = fmaxf(m, sdyn[j * 26 + k]);
        float e[JJ]; float s = 0.f;
#pragma unroll
        for (int k = 0; k < JJ; k++) { e[k] = expf(sdyn[j * 26 + k] - m); s += e[k]; }
        float inv = 1.0f / s;
#pragma unroll
        for (int k = 0; k < JJ; k++) sdyn[j * 26 + k] = e[k] * inv;
    }
    __syncthreads();
    {   // E16 hi/lo + csf
        const float* sdyn = (const float*)(sm + P_SD);
        __half* eh = (__half*)(sm + SM_E16H);
        __half* el = (__half*)(sm + SM_E16L);
        for (int i = tid; i < 32 * XP; i += 512) {
            int j = i / XP, n = i - j * XP;
            float v = 0.f;
            if (j < JJ && n < JJ) {
                float a = 0.f;
#pragma unroll
                for (int m2 = 0; m2 < JJ; m2++) a = fmaf(adj[j * JJ + m2], sdyn[m2 * 26 + n], a);
                v = adj[j * JJ + n] + alpha * a;
            }
            __half h = __float2half_rn(v);
            eh[i] = h;
            el[i] = __float2half_rn(v - __half2float(h));
        }
        float* csf = (float*)(sm + SM_CSF);
        if (tid < 32) {
            float v = 0.f;
            if (tid < JJ) {
                float a = 0.f;
#pragma unroll
                for (int j = 0; j < JJ; j++) a += sdyn[j * 26 + tid];
                v = 1.0f + alpha * a;
            }
            csf[tid] = v;
        }
    }
    __syncthreads();

    // ======== main pipeline (round-10 verbatim) ========
    float* csf = (float*)(sm + SM_CSF);

    if (!is_prod) {
        // ===== CONSUMERS (warps 0..7): Ahi-resident pipelined GEMM + epilogue =====
        int warp = tid >> 5, lane = tid & 31;
        int o0 = warp * 16;
        int gid = lane >> 2, tig = lane & 3;
        u32 arow  = (u32)(o0 + (lane & 15));
        u32 acsel = (u32)((lane >> 4) * 8);
        u32 brow  = (u32)((lane & 7) + ((lane >> 3) & 1) * 8);
        u32 bcsel = (u32)((lane >> 4) * 8);
        u32 brow2 = (u32)(lane & 15);
        int o_a = o0 + gid, o_b = o_a + 8;
        float ck = csf[lane & 31];
        float* outb = out + (size_t)b * 409600;
        const float4* sbn = (const float4*)(sm + SM_SBN);

        u32 AbH = sbase + (u32)SM_A_HI + (arow * AP + acsel) * 2;
        u32 AbL = sbase + (u32)SM_A_LO + (arow * AP + acsel) * 2;

        u32 fahi[8][4];
#pragma unroll
        for (int kt = 0; kt < 8; ++kt) ldsm_x4(fahi[kt], AbH + (u32)(kt * 32));

        for (int ch = 0; ch < NCHUNK; ++ch) {
            int cbuf = ch & 1;
            BAR_SYNC(BAR_FULL(cbuf), 512);

            u32 BbH = sbase + (u32)SM_BH(cbuf);
            u32 BbL = sbase + (u32)SM_BL(cbuf);
            u32 BroH  = BbH + (brow * BP + bcsel) * 2;
            u32 BroL  = BbL + (brow * BP + bcsel) * 2;
            u32 Bro2H = BbH + (brow2 * BP + 48u) * 2;
            u32 Bro2L = BbL + (brow2 * BP + 48u) * 2;

            float acc[NTILES][4];
#pragma unroll
            for (int nt = 0; nt < NTILES; ++nt)
#pragma unroll
                for (int r = 0; r < 4; ++r) acc[nt][r] = 0.f;

            u32 bhi[2][14], blo[14], alo[4];
#define LDBHI(pb, kt) do {                                                  \
    u32 kb = (u32)((kt) * 16 * BP * 2);                                     \
    ldsm_x4t(&bhi[pb][0],  BroH + kb);                                      \
    ldsm_x4t(&bhi[pb][4],  BroH + kb + 32u);                                \
    ldsm_x4t(&bhi[pb][8],  BroH + kb + 64u);                                \
    ldsm_x2t(&bhi[pb][12], Bro2H + kb);                                     \
} while (0)
#define LDBLO(kt) do {                                                      \
    u32 kb = (u32)((kt) * 16 * BP * 2);                                     \
    ldsm_x4t(&blo[0],  BroL + kb);                                          \
    ldsm_x4t(&blo[4],  BroL + kb + 32u);                                    \
    ldsm_x4t(&blo[8],  BroL + kb + 64u);                                    \
    ldsm_x2t(&blo[12], Bro2L + kb);                                         \
} while (0)
            LDBHI(0, 0);
#pragma unroll
            for (int kt = 0; kt < 8; ++kt) {
                int pb = kt & 1;
                LDBLO(kt);
                ldsm_x4(alo, AbL + (u32)(kt * 32));
                mma_fp16(acc[0], fahi[kt], &bhi[pb][0]);
                mma_fp16(acc[1], fahi[kt], &bhi[pb][2]);
                mma_fp16(acc[2], fahi[kt], &bhi[pb][4]);
                mma_fp16(acc[3], fahi[kt], &bhi[pb][6]);
                mma_fp16(acc[4], fahi[kt], &bhi[pb][8]);
                mma_fp16(acc[5], fahi[kt], &bhi[pb][10]);
                mma_fp16(acc[6], fahi[kt], &bhi[pb][12]);
                if (kt < 7) LDBHI(pb ^ 1, kt + 1);
                mma_fp16(acc[0], alo, &bhi[pb][0]);
                mma_fp16(acc[1], alo, &bhi[pb][2]);
                mma_fp16(acc[2], alo, &bhi[pb][4]);
                mma_fp16(acc[3], alo, &bhi[pb][6]);
                mma_fp16(acc[4], alo, &bhi[pb][8]);
                mma_fp16(acc[5], alo, &bhi[pb][10]);
                mma_fp16(acc[6], alo, &bhi[pb][12]);
                mma_fp16(acc[0], fahi[kt], &blo[0]);
                mma_fp16(acc[1], fahi[kt], &blo[2]);
                mma_fp16(acc[2], fahi[kt], &blo[4]);
                mma_fp16(acc[3], fahi[kt], &blo[6]);
                mma_fp16(acc[4], fahi[kt], &blo[8]);
                mma_fp16(acc[5], fahi[kt], &blo[10]);
                mma_fp16(acc[6], fahi[kt], &blo[12]);
            }
#undef LDBHI
#undef LDBLO

            BAR_SYNC(BAR_CONS, 256);
            float* D = (float*)(sm + SM_BH(cbuf));
#pragma unroll
            for (int nt = 0; nt < NTILES; ++nt) {
                int n0 = nt * 8 + tig * 2;
                D[o_a * 56 + n0]     = acc[nt][0];
                D[o_a * 56 + n0 + 1] = acc[nt][1];
                D[o_b * 56 + n0]     = acc[nt][2];
                D[o_b * 56 + n0 + 1] = acc[nt][3];
            }
            BAR_SYNC(BAR_CONS, 256);

            int tch = t0slab + ch * CHT;
#pragma unroll
            for (int rr = 0; rr < 32; ++rr) {
                int idx = warp * 32 + rr;
                int o = idx >> 1, tl = idx & 1;
                float4 bn = sbn[o];
                if (lane < JJ) {
                    float v = D[o * 56 + tl * 26 + lane];
                    float pre = fmaf(bn.z, ck, v);
                    outb[(size_t)o * 3200 + (tch + tl) * 25 + lane] =
                        fmaxf(fmaf(pre, bn.x, bn.y), 0.f);
                }
            }
            BAR_ARRIVE(BAR_FREE(cbuf), 512);
        }
    } else {
        // ===== PRODUCERS (warps 8..15): cvt + mix-MMA =====
        int pw = (tid >> 5) - 8;
        int lane = tid & 31;
        int mbase = 32 * pw;
        u32 xrow  = (u32)(lane & 15);
        u32 xcsel = (u32)((lane >> 4) * 8);
        u32 erow  = (u32)((lane & 7) + ((lane >> 3) & 1) * 8);
        u32 ecsel = (u32)((lane >> 4) * 8);
        int r_cv = ptid, c_cv = r_cv >> 1, t_cv = r_cv & 1;

        for (int ch = 0; ch < NCHUNK; ++ch) {
            int buf = ch & 1;
            if (ch < NCHUNK - 2) { CP_WAIT1(); } else { CP_WAITALL(); }
            BAR_SYNC(BAR_PROD, 256);

            {
                const float* xr = (const float*)(sm + SM_RAW(buf)) + c_cv * RAWP + t_cv * 25;
#pragma unroll
                for (int s = 0; s < 4; ++s) {
                    u32 hi[4], lo[4];
#pragma unroll
                    for (int qq2 = 0; qq2 < 4; ++qq2) {
                        int q = 4 * s + qq2;
                        float f0 = (2 * q < 25) ? xr[2 * q] : 0.f;
                        float f1 = (2 * q + 1 < 25) ? xr[2 * q + 1] : 0.f;
                        __half h0 = __float2half_rn(f0), h1 = __float2half_rn(f1);
                        hi[qq2] = (u32)__half_as_ushort(h0) | ((u32)__half_as_ushort(h1) << 16);
                        lo[qq2] = packh(f0 - __half2float(h0), f1 - __half2float(h1));
                    }
                    *(uint4*)(sm + SM_X_HI + r_cv * 80 + s * 16) = make_uint4(hi[0], hi[1], hi[2], hi[3]);
                    *(uint4*)(sm + SM_X_LO + r_cv * 80 + s * 16) = make_uint4(lo[0], lo[1], lo[2], lo[3]);
                }
            }
            BAR_SYNC(BAR_PROD, 256);

            if (ch + 2 < NCHUNK) {
#pragma unroll
                for (int k = 0; k < 25; ++k) {
                    int flat = ptid + 256 * k;
                    int c = flat / 50, col = flat - 50 * c;
                    cp4(sbase + SM_RAW(buf) + (u32)((c * RAWP + col) * 4),
                        xb + (size_t)c * 3200 + (ch + 2) * 50 + col);
                }
                CP_COMMIT();
            }

            if (ch >= 2) BAR_SYNC(BAR_FREE(buf), 512);

            char* bh = sm + SM_BH(buf);
            char* bl = sm + SM_BL(buf);
#pragma unroll
            for (int mt = 0; mt < 2; ++mt) {
                u32 ro = (u32)((mbase + mt * 16) + xrow);
                u32 xfH[2][4], xfL[2][4], ef[2][2][4];
                float accm[4][4];
#pragma unroll
                for (int nt = 0; nt < 4; ++nt)
#pragma unroll
                    for (int r = 0; r < 4; ++r) accm[nt][r] = 0.f;
#pragma unroll
                for (int kt = 0; kt < 2; ++kt) {
                    ldsm_x4(xfH[kt], sbase + (u32)SM_X_HI + (ro * XP + (u32)(kt * 16) + xcsel) * 2);
                    ldsm_x4(xfL[kt], sbase + (u32)SM_X_LO + (ro * XP + (u32)(kt * 16) + xcsel) * 2);
                }
#pragma unroll
                for (int kt = 0; kt < 2; ++kt)
#pragma unroll
                    for (int n2 = 0; n2 < 2; ++n2)
                        ldsm_x4t(ef[kt][n2], sbase + (u32)SM_E16H +
                                 (((u32)(kt * 16) + erow) * XP + (u32)(n2 * 16) + ecsel) * 2);
#pragma unroll
                for (int kt = 0; kt < 2; ++kt)
#pragma unroll
                    for (int n2 = 0; n2 < 2; ++n2) {
                        mma_fp16(accm[2 * n2],     xfH[kt], ef[kt][n2]);
                        mma_fp16(accm[2 * n2 + 1], xfH[kt], ef[kt][n2] + 2);
                        mma_fp16(accm[2 * n2],     xfL[kt], ef[kt][n2]);
                        mma_fp16(accm[2 * n2 + 1], xfL[kt], ef[kt][n2] + 2);
                    }
#pragma unroll
                for (int kt = 0; kt < 2; ++kt)
#pragma unroll
                    for (int n2 = 0; n2 < 2; ++n2)
                        ldsm_x4t(ef[kt][n2], sbase + (u32)SM_E16L +
                                 (((u32)(kt * 16) + erow) * XP + (u32)(n2 * 16) + ecsel) * 2);
#pragma unroll
                for (int kt = 0; kt < 2; ++kt)
#pragma unroll
                    for (int n2 = 0; n2 < 2; ++n2) {
                        mma_fp16(accm[2 * n2],     xfH[kt], ef[kt][n2]);
                        mma_fp16(accm[2 * n2 + 1], xfH[kt], ef[kt][n2] + 2);
                    }

#pragma unroll
                for (int nt = 0; nt < 4; ++nt) {
                    int n0 = nt * 8 + (lane & 3) * 2;
                    if (n0 < 26) {
                        int rA = mbase + mt * 16 + (lane >> 2);
                        int rB = rA + 8;
                        {
                            int cc = rA >> 1, tl = rA & 1;
                            u32 off = (u32)((cc * BP + tl * 26 + n0) * 2);
                            float a0 = accm[nt][0], a1 = accm[nt][1];
                            __half h0 = __float2half_rn(a0), h1 = __float2half_rn(a1);
                            *(u32*)(bh + off) = (u32)__half_as_ushort(h0) | ((u32)__half_as_ushort(h1) << 16);
                            *(u32*)(bl + off) = packh(a0 - __half2float(h0), a1 - __half2float(h1));
                        }
                        {
                            int cc = rB >> 1, tl = rB & 1;
                            u32 off = (u32)((cc * BP + tl * 26 + n0) * 2);
                            float a0 = accm[nt][2], a1 = accm[nt][3];
                            __half h0 = __float2half_rn(a0), h1 = __float2half_rn(a1);
                            *(u32*)(bh + off) = (u32)__half_as_ushort(h0) | ((u32)__half_as_ushort(h1) << 16);
                            *(u32*)(bl + off) = packh(a0 - __half2float(h0), a1 - __half2float(h1));
                        }
                    }
                }
            }
            BAR_ARRIVE(BAR_FULL(buf), 512);
        }
    }
}

// ---------------- launch ----------------
extern "C" void kernel_launch(void* const* d_in, const int* in_sizes, int n_in,
                              void* d_out, int out_size) {
    const float* x     = (const float*)d_in[0];
    const float* adj   = (const float*)d_in[1];
    const float* Wk    = (const float*)d_in[2];
    const float* bk    = (const float*)d_in[3];
    const float* Wq    = (const float*)d_in[4];
    const float* bq    = (const float*)d_in[5];
    const float* Ws    = (const float*)d_in[6];
    const float* bs    = (const float*)d_in[7];
    const float* gamma = (const float*)d_in[8];
    const float* beta  = (const float*)d_in[9];
    const float* rmean = (const float*)d_in[10];
    const float* rvar  = (const float*)d_in[11];
    const float* alpha = (const float*)d_in[12];
    float* out = (float*)d_out;

    cudaFuncSetAttribute(k3_main, cudaFuncAttributeMaxDynamicSharedMemorySize, SMEM_TOTAL);

    k1_mean<<<dim3(8, NB), 256>>>(x);
    k3_main<<<dim3(TT / TSLAB, NB), 512, SMEM_TOTAL>>>(
        x, Ws, bs, gamma, beta, rmean, rvar, out, adj, Wk, bk, Wq, bq, alpha);
}

// round 14
// speedup vs baseline: 1.9534x; 1.9534x over previous
#include <cuda_runtime.h>
#include <cuda_fp16.h>

typedef unsigned int u32;
typedef unsigned long long u64;

#define NB 64
#define CIN 128
#define COUT 128
#define TT 128
#define JJ 25

#define TSLAB 64            // t's per CTA -> 128 CTAs total, 1 wave
#define CHT 2
#define NCHUNK 32
#define NTILES 7
#define AP 136
#define BP 56
#define RAWP 51
#define XP 40

// ---- smem byte offsets (round-10 layout) ----
#define SM_CSF   0
#define SM_SBN   128
#define SM_E16H  2176
#define SM_E16L  4736
#define SM_A_HI  7296
#define SM_A_LO  42112
#define SM_B0    76928
#define B_HALF   14336
#define B_BUF    28672
#define SM_BH(b) (SM_B0 + (b)*B_BUF)
#define SM_BL(b) (SM_BH(b) + B_HALF)
#define SM_X_HI  134272
#define SM_X_LO  154752
#define SM_RAW0  175232
#define RAW_BYTES 26112
#define SM_RAW(b) (SM_RAW0 + (b)*RAW_BYTES)
#define SMEM_TOTAL 227456

// named barrier ids
#define BAR_FULL(b) (1 + (b))
#define BAR_FREE(b) (3 + (b))
#define BAR_PROD    5
#define BAR_CONS    6

// ---------------- scratch ----------------
__device__ float g_xt_mean[NB * CIN * JJ];
__device__ float g_E[NB * JJ * JJ];
__device__ float g_csf[NB * JJ];

// ---------------- helpers ----------------
__device__ __forceinline__ u32 smem_u32(const void* p) {
    u32 a; asm("{ .reg .u64 t; cvta.to.shared.u64 t, %1; cvt.u32.u64 %0, t; }" : "=r"(a) : "l"(p));
    return a;
}
__device__ __forceinline__ void ldsm_x4(u32* r, u32 addr) {
    asm volatile("ldmatrix.sync.aligned.m8n8.x4.shared.b16 {%0,%1,%2,%3}, [%4];"
        : "=r"(r[0]), "=r"(r[1]), "=r"(r[2]), "=r"(r[3]) : "r"(addr) : "memory");
}
__device__ __forceinline__ void ldsm_x4t(u32* r, u32 addr) {
    asm volatile("ldmatrix.sync.aligned.m8n8.x4.trans.shared.b16 {%0,%1,%2,%3}, [%4];"
        : "=r"(r[0]), "=r"(r[1]), "=r"(r[2]), "=r"(r[3]) : "r"(addr) : "memory");
}
__device__ __forceinline__ void ldsm_x2t(u32* r, u32 addr) {
    asm volatile("ldmatrix.sync.aligned.m8n8.x2.trans.shared.b16 {%0,%1}, [%2];"
        : "=r"(r[0]), "=r"(r[1]) : "r"(addr) : "memory");
}
__device__ __forceinline__ void mma_fp16(float* d, const u32* a, const u32* b) {
    asm volatile("mma.sync.aligned.m16n8k16.row.col.f32.f16.f16.f32 "
        "{%0,%1,%2,%3}, {%4,%5,%6,%7}, {%8,%9}, {%0,%1,%2,%3};"
        : "+f"(d[0]), "+f"(d[1]), "+f"(d[2]), "+f"(d[3])
        : "r"(a[0]), "r"(a[1]), "r"(a[2]), "r"(a[3]), "r"(b[0]), "r"(b[1]));
}
__device__ __forceinline__ void cp4(u32 dst, const void* src) {
    asm volatile("cp.async.ca.shared.global [%0], [%1], 4;" :: "r"(dst), "l"(src) : "memory");
}
#define CP_COMMIT() asm volatile("cp.async.commit_group;" ::: "memory")
#define CP_WAIT1()  asm volatile("cp.async.wait_group 1;" ::: "memory")
#define CP_WAITALL() asm volatile("cp.async.wait_group 0;" ::: "memory")
#define BAR_SYNC(id, cnt) asm volatile("bar.sync %0, %1;" :: "r"(id), "r"(cnt) : "memory")
#define BAR_ARRIVE(id, cnt) asm volatile("bar.arrive %0, %1;" :: "r"(id), "r"(cnt) : "memory")

__device__ __forceinline__ u32 packh(float a, float b) {
    __half h0 = __float2half_rn(a), h1 = __float2half_rn(b);
    return (u32)__half_as_ushort(h0) | ((u32)__half_as_ushort(h1) << 16);
}

// ---------------- K1: temporal mean (2 channels / warp) ----------------
__global__ void k1_mean(const float* __restrict__ x) {
    int b = blockIdx.y;
    int c0 = blockIdx.x * 16 + (threadIdx.x >> 5) * 2;
    int j = threadIdx.x & 31;
    if (j >= JJ) return;
    const float* p0 = x + ((size_t)(b * CIN + c0) * TT) * JJ + j;
    const float* p1 = p0 + (size_t)TT * JJ;
    float a0 = 0.f, a1 = 0.f, a2 = 0.f, a3 = 0.f;
    float b0 = 0.f, b1 = 0.f, b2 = 0.f, b3 = 0.f;
#pragma unroll 8
    for (int t = 0; t < TT; t += 4) {
        a0 += p0[t * JJ];       b0 += p1[t * JJ];
        a1 += p0[(t + 1) * JJ]; b1 += p1[(t + 1) * JJ];
        a2 += p0[(t + 2) * JJ]; b2 += p1[(t + 2) * JJ];
        a3 += p0[(t + 3) * JJ]; b3 += p1[(t + 3) * JJ];
    }
    g_xt_mean[(b * CIN + c0) * JJ + j]     = ((a0 + a1) + (a2 + a3)) * (1.0f / TT);
    g_xt_mean[(b * CIN + c0 + 1) * JJ + j] = ((b0 + b1) + (b2 + b3)) * (1.0f / TT);
}

// ---------------- K2: per-batch attention (256 thr, j-split GEMV) ----------------
__global__ void k2_attn(const float* __restrict__ adj,
                        const float* __restrict__ Wk, const float* __restrict__ bk,
                        const float* __restrict__ Wq, const float* __restrict__ bq,
                        const float* __restrict__ alphaPtr) {
    int b = blockIdx.x;
    int tid = threadIdx.x;  // 256
    __shared__ float xt[CIN * 26];
    __shared__ float skk[COUT * 26];
    __shared__ float sqq[COUT * 26];
    __shared__ float sdyn[JJ * 26];

    for (int i = tid; i < CIN * JJ; i += 256) {
        int c = i / JJ, j = i - c * JJ;
        xt[c * 26 + j] = g_xt_mean[b * CIN * JJ + i];
    }
    __syncthreads();
    {
        int o = tid >> 1, half = tid & 1;
        int j0 = half * 13;
        int nj = half ? 12 : 13;
        const float4* wk4 = (const float4*)(Wk + o * CIN);
        const float4* wq4 = (const float4*)(Wq + o * CIN);
        float ak[13], aq[13];
#pragma unroll
        for (int jj = 0; jj < 13; ++jj) { ak[jj] = 0.f; aq[jj] = 0.f; }
#pragma unroll 4
        for (int c4 = 0; c4 < CIN / 4; ++c4) {
            float4 wk = wk4[c4], wq = wq4[c4];
            const float* x0 = &xt[(c4 * 4) * 26] + j0;
#pragma unroll
            for (int jj = 0; jj < 13; ++jj) {
                if (jj < nj) {
                    float v0 = x0[jj], v1 = x0[26 + jj], v2 = x0[52 + jj], v3 = x0[78 + jj];
                    float a = ak[jj], q = aq[jj];
                    a = fmaf(wk.x, v0, a); q = fmaf(wq.x, v0, q);
                    a = fmaf(wk.y, v1, a); q = fmaf(wq.y, v1, q);
                    a = fmaf(wk.z, v2, a); q = fmaf(wq.z, v2, q);
                    a = fmaf(wk.w, v3, a); q = fmaf(wq.w, v3, q);
                    ak[jj] = a; aq[jj] = q;
                }
            }
        }
        float bko = bk[o], bqo = bq[o];
#pragma unroll
        for (int jj = 0; jj < 13; ++jj)
            if (jj < nj) {
                skk[o * 26 + j0 + jj] = ak[jj] + bko;
                sqq[o * 26 + j0 + jj] = aq[jj] + bqo;
            }
    }
    __syncthreads();
    const float inv_scale = 0.08838834764831843f;  // 1/sqrt(128)
    for (int i = tid; i < JJ * JJ; i += 256) {
        int j = i / JJ, k = i - j * JJ;
        float acc = 0.f;
        for (int o = 0; o < COUT; o++) acc = fmaf(sqq[o * 26 + j], skk[o * 26 + k], acc);
        sdyn[j * 26 + k] = acc * inv_scale;
    }
    __syncthreads();
    if (tid < JJ) {
        int j = tid;
        float m = -1e30f;
#pragma unroll
        for (int k = 0; k < JJ; k++) m = fmaxf(m, sdyn[j * 26 + k]);
        float e[JJ]; float s = 0.f;
#pragma unroll
        for (int k = 0; k < JJ; k++) { e[k] = expf(sdyn[j * 26 + k] - m); s += e[k]; }
        float inv = 1.0f / s;
#pragma unroll
        for (int k = 0; k < JJ; k++) sdyn[j * 26 + k] = e[k] * inv;
    }
    __syncthreads();
    float alpha = alphaPtr[0];
    for (int i = tid; i < JJ * JJ; i += 256) {
        int j = i / JJ, k = i - j * JJ;
        float acc = 0.f;
#pragma unroll
        for (int m2 = 0; m2 < JJ; m2++) acc = fmaf(adj[j * JJ + m2], sdyn[m2 * 26 + k], acc);
        g_E[b * JJ * JJ + i] = adj[j * JJ + k] + alpha * acc;
    }
    if (tid < JJ) {
        int k = tid;
        float acc = 0.f;
#pragma unroll
        for (int j = 0; j < JJ; j++) acc += sdyn[j * 26 + k];
        g_csf[b * JJ + k] = 1.0f + alpha * acc;
    }
}

// ---------------- K3 (round-10 verbatim, TSLAB=64) ----------------
__global__ void __launch_bounds__(512, 1)
k3_main(const float* __restrict__ x, const float* __restrict__ Ws,
        const float* __restrict__ bs, const float* __restrict__ gamma,
        const float* __restrict__ beta, const float* __restrict__ rmean,
        const float* __restrict__ rvar, float* __restrict__ out) {
    extern __shared__ char sm[];
    u32 sbase = smem_u32(sm);
    int tid = threadIdx.x;
    int b = blockIdx.y, slab = blockIdx.x;
    int t0slab = slab * TSLAB;

    bool is_prod = tid >= 256;
    int ptid = tid & 255;
    const float* xb = x + (size_t)b * 409600 + (size_t)t0slab * 25;

    // ---- producers: cp.async raw chunks 0,1 ----
    if (is_prod) {
#pragma unroll
        for (int cb = 0; cb < 2; ++cb) {
#pragma unroll
            for (int k = 0; k < 25; ++k) {
                int flat = ptid + 256 * k;
                int c = flat / 50, col = flat - 50 * c;
                cp4(sbase + SM_RAW(cb) + (u32)((c * RAWP + col) * 4),
                    xb + (size_t)c * 3200 + cb * 50 + col);
            }
            CP_COMMIT();
        }
    }

    // ---- staging (all 512 threads) ----
    float* csf = (float*)(sm + SM_CSF);
    if (tid < 32) csf[tid] = (tid < JJ) ? g_csf[b * JJ + tid] : 0.f;
    if (tid >= 32 && tid < 160) {
        int o = tid - 32;
        float inv = gamma[o] * rsqrtf(rvar[o] + 1e-5f);
        float sh = beta[o] - rmean[o] * inv;
        ((float4*)(sm + SM_SBN))[o] = make_float4(inv, sh, bs[o], 0.f);
    }
    {
        __half* eh = (__half*)(sm + SM_E16H);
        __half* el = (__half*)(sm + SM_E16L);
        for (int i = tid; i < 32 * XP; i += 512) {
            int j = i / XP, n = i - j * XP;
            float v = (j < JJ && n < JJ) ? g_E[b * 625 + j * 25 + n] : 0.f;
            __half h = __float2half_rn(v);
            eh[i] = h;
            el[i] = __float2half_rn(v - __half2float(h));
        }
    }
    {
        __half* ah = (__half*)(sm + SM_A_HI);
        __half* al = (__half*)(sm + SM_A_LO);
        for (int i = tid; i < COUT * CIN; i += 512) {
            int o = i >> 7, c = i & 127;
            float v = Ws[i];
            __half hb = __float2half_rn(v);
            ah[o * AP + c] = hb;
            al[o * AP + c] = __float2half_rn(v - __half2float(hb));
        }
    }
    __syncthreads();

    if (!is_prod) {
        // ===== CONSUMERS (warps 0..7): Ahi-resident pipelined GEMM + epilogue =====
        int warp = tid >> 5, lane = tid & 31;
        int o0 = warp * 16;
        int gid = lane >> 2, tig = lane & 3;
        u32 arow  = (u32)(o0 + (lane & 15));
        u32 acsel = (u32)((lane >> 4) * 8);
        u32 brow  = (u32)((lane & 7) + ((lane >> 3) & 1) * 8);
        u32 bcsel = (u32)((lane >> 4) * 8);
        u32 brow2 = (u32)(lane & 15);
        int o_a = o0 + gid, o_b = o_a + 8;
        float ck = csf[lane & 31];
        float* outb = out + (size_t)b * 409600;
        const float4* sbn = (const float4*)(sm + SM_SBN);

        u32 AbH = sbase + (u32)SM_A_HI + (arow * AP + acsel) * 2;
        u32 AbL = sbase + (u32)SM_A_LO + (arow * AP + acsel) * 2;

        u32 fahi[8][4];
#pragma unroll
        for (int kt = 0; kt < 8; ++kt) ldsm_x4(fahi[kt], AbH + (u32)(kt * 32));

        for (int ch = 0; ch < NCHUNK; ++ch) {
            int cbuf = ch & 1;
            BAR_SYNC(BAR_FULL(cbuf), 512);

            u32 BbH = sbase + (u32)SM_BH(cbuf);
            u32 BbL = sbase + (u32)SM_BL(cbuf);
            u32 BroH  = BbH + (brow * BP + bcsel) * 2;
            u32 BroL  = BbL + (brow * BP + bcsel) * 2;
            u32 Bro2H = BbH + (brow2 * BP + 48u) * 2;
            u32 Bro2L = BbL + (brow2 * BP + 48u) * 2;

            float acc[NTILES][4];
#pragma unroll
            for (int nt = 0; nt < NTILES; ++nt)
#pragma unroll
                for (int r = 0; r < 4; ++r) acc[nt][r] = 0.f;

            u32 bhi[2][14], blo[14], alo[4];
#define LDBHI(pb, kt) do {                                                  \
    u32 kb = (u32)((kt) * 16 * BP * 2);                                     \
    ldsm_x4t(&bhi[pb][0],  BroH + kb);                                      \
    ldsm_x4t(&bhi[pb][4],  BroH + kb + 32u);                                \
    ldsm_x4t(&bhi[pb][8],  BroH + kb + 64u);                                \
    ldsm_x2t(&bhi[pb][12], Bro2H + kb);                                     \
} while (0)
#define LDBLO(kt) do {                                                      \
    u32 kb = (u32)((kt) * 16 * BP * 2);                                     \
    ldsm_x4t(&blo[0],  BroL + kb);                                          \
    ldsm_x4t(&blo[4],  BroL + kb + 32u);                                    \
    ldsm_x4t(&blo[8],  BroL + kb + 64u);                                    \
    ldsm_x2t(&blo[12], Bro2L + kb);                                         \
} while (0)
            LDBHI(0, 0);
#pragma unroll
            for (int kt = 0; kt < 8; ++kt) {
                int pb = kt & 1;
                LDBLO(kt);
                ldsm_x4(alo, AbL + (u32)(kt * 32));
                mma_fp16(acc[0], fahi[kt], &bhi[pb][0]);
                mma_fp16(acc[1], fahi[kt], &bhi[pb][2]);
                mma_fp16(acc[2], fahi[kt], &bhi[pb][4]);
                mma_fp16(acc[3], fahi[kt], &bhi[pb][6]);
                mma_fp16(acc[4], fahi[kt], &bhi[pb][8]);
                mma_fp16(acc[5], fahi[kt], &bhi[pb][10]);
                mma_fp16(acc[6], fahi[kt], &bhi[pb][12]);
                if (kt < 7) LDBHI(pb ^ 1, kt + 1);
                mma_fp16(acc[0], alo, &bhi[pb][0]);
                mma_fp16(acc[1], alo, &bhi[pb][2]);
                mma_fp16(acc[2], alo, &bhi[pb][4]);
                mma_fp16(acc[3], alo, &bhi[pb][6]);
                mma_fp16(acc[4], alo, &bhi[pb][8]);
                mma_fp16(acc[5], alo, &bhi[pb][10]);
                mma_fp16(acc[6], alo, &bhi[pb][12]);
                mma_fp16(acc[0], fahi[kt], &blo[0]);
                mma_fp16(acc[1], fahi[kt], &blo[2]);
                mma_fp16(acc[2], fahi[kt], &blo[4]);
                mma_fp16(acc[3], fahi[kt], &blo[6]);
                mma_fp16(acc[4], fahi[kt], &blo[8]);
                mma_fp16(acc[5], fahi[kt], &blo[10]);
                mma_fp16(acc[6], fahi[kt], &blo[12]);
            }
#undef LDBHI
#undef LDBLO

            BAR_SYNC(BAR_CONS, 256);
            float* D = (float*)(sm + SM_BH(cbuf));
#pragma unroll
            for (int nt = 0; nt < NTILES; ++nt) {
                int n0 = nt * 8 + tig * 2;
                D[o_a * 56 + n0]     = acc[nt][0];
                D[o_a * 56 + n0 + 1] = acc[nt][1];
                D[o_b * 56 + n0]     = acc[nt][2];
                D[o_b * 56 + n0 + 1] = acc[nt][3];
            }
            BAR_SYNC(BAR_CONS, 256);

            int tch = t0slab + ch * CHT;
#pragma unroll
            for (int rr = 0; rr < 32; ++rr) {
                int idx = warp * 32 + rr;
                int o = idx >> 1, tl = idx & 1;
                float4 bn = sbn[o];
                if (lane < JJ) {
                    float v = D[o * 56 + tl * 26 + lane];
                    float pre = fmaf(bn.z, ck, v);
                    outb[(size_t)o * 3200 + (tch + tl) * 25 + lane] =
                        fmaxf(fmaf(pre, bn.x, bn.y), 0.f);
                }
            }
            BAR_ARRIVE(BAR_FREE(cbuf), 512);
        }
    } else {
        // ===== PRODUCERS (warps 8..15): cvt + mix-MMA =====
        int pw = (tid >> 5) - 8;
        int lane = tid & 31;
        int mbase = 32 * pw;
        u32 xrow  = (u32)(lane & 15);
        u32 xcsel = (u32)((lane >> 4) * 8);
        u32 erow  = (u32)((lane & 7) + ((lane >> 3) & 1) * 8);
        u32 ecsel = (u32)((lane >> 4) * 8);
        int r_cv = ptid, c_cv = r_cv >> 1, t_cv = r_cv & 1;

        for (int ch = 0; ch < NCHUNK; ++ch) {
            int buf = ch & 1;
            if (ch < NCHUNK - 2) { CP_WAIT1(); } else { CP_WAITALL(); }
            BAR_SYNC(BAR_PROD, 256);

            {
                const float* xr = (const float*)(sm + SM_RAW(buf)) + c_cv * RAWP + t_cv * 25;
#pragma unroll
                for (int s = 0; s < 4; ++s) {
                    u32 hi[4], lo[4];
#pragma unroll
                    for (int qq = 0; qq < 4; ++qq) {
                        int q = 4 * s + qq;
                        float f0 = (2 * q < 25) ? xr[2 * q] : 0.f;
                        float f1 = (2 * q + 1 < 25) ? xr[2 * q + 1] : 0.f;
                        __half h0 = __float2half_rn(f0), h1 = __float2half_rn(f1);
                        hi[qq] = (u32)__half_as_ushort(h0) | ((u32)__half_as_ushort(h1) << 16);
                        lo[qq] = packh(f0 - __half2float(h0), f1 - __half2float(h1));
                    }
                    *(uint4*)(sm + SM_X_HI + r_cv * 80 + s * 16) = make_uint4(hi[0], hi[1], hi[2], hi[3]);
                    *(uint4*)(sm + SM_X_LO + r_cv * 80 + s * 16) = make_uint4(lo[0], lo[1], lo[2], lo[3]);
                }
            }
            BAR_SYNC(BAR_PROD, 256);

            if (ch + 2 < NCHUNK) {
#pragma unroll
                for (int k = 0; k < 25; ++k) {
                    int flat = ptid + 256 * k;
                    int c = flat / 50, col = flat - 50 * c;
                    cp4(sbase + SM_RAW(buf) + (u32)((c * RAWP + col) * 4),
                        xb + (size_t)c * 3200 + (ch + 2) * 50 + col);
                }
                CP_COMMIT();
            }

            if (ch >= 2) BAR_SYNC(BAR_FREE(buf), 512);

            char* bh = sm + SM_BH(buf);
            char* bl = sm + SM_BL(buf);
#pragma unroll
            for (int mt = 0; mt < 2; ++mt) {
                u32 ro = (u32)((mbase + mt * 16) + xrow);
                u32 xfH[2][4], xfL[2][4], ef[2][2][4];
                float accm[4][4];
#pragma unroll
                for (int nt = 0; nt < 4; ++nt)
#pragma unroll
                    for (int r = 0; r < 4; ++r) accm[nt][r] = 0.f;
#pragma unroll
                for (int kt = 0; kt < 2; ++kt) {
                    ldsm_x4(xfH[kt], sbase + (u32)SM_X_HI + (ro * XP + (u32)(kt * 16) + xcsel) * 2);
                    ldsm_x4(xfL[kt], sbase + (u32)SM_X_LO + (ro * XP + (u32)(kt * 16) + xcsel) * 2);
                }
#pragma unroll
                for (int kt = 0; kt < 2; ++kt)
#pragma unroll
                    for (int n2 = 0; n2 < 2; ++n2)
                        ldsm_x4t(ef[kt][n2], sbase + (u32)SM_E16H +
                                 (((u32)(kt * 16) + erow) * XP + (u32)(n2 * 16) + ecsel) * 2);
#pragma unroll
                for (int kt = 0; kt < 2; ++kt)
#pragma unroll
                    for (int n2 = 0; n2 < 2; ++n2) {
                        mma_fp16(accm[2 * n2],     xfH[kt], ef[kt][n2]);
                        mma_fp16(accm[2 * n2 + 1], xfH[kt], ef[kt][n2] + 2);
                        mma_fp16(accm[2 * n2],     xfL[kt], ef[kt][n2]);
                        mma_fp16(accm[2 * n2 + 1], xfL[kt], ef[kt][n2] + 2);
                    }
#pragma unroll
                for (int kt = 0; kt < 2; ++kt)
#pragma unroll
                    for (int n2 = 0; n2 < 2; ++n2)
                        ldsm_x4t(ef[kt][n2], sbase + (u32)SM_E16L +
                                 (((u32)(kt * 16) + erow) * XP + (u32)(n2 * 16) + ecsel) * 2);
#pragma unroll
                for (int kt = 0; kt < 2; ++kt)
#pragma unroll
                    for (int n2 = 0; n2 < 2; ++n2) {
                        mma_fp16(accm[2 * n2],     xfH[kt], ef[kt][n2]);
                        mma_fp16(accm[2 * n2 + 1], xfH[kt], ef[kt][n2] + 2);
                    }

#pragma unroll
                for (int nt = 0; nt < 4; ++nt) {
                    int n0 = nt * 8 + (lane & 3) * 2;
                    if (n0 < 26) {
                        int rA = mbase + mt * 16 + (lane >> 2);
                        int rB = rA + 8;
                        {
                            int cc = rA >> 1, tl = rA & 1;
                            u32 off = (u32)((cc * BP + tl * 26 + n0) * 2);
                            float a0 = accm[nt][0], a1 = accm[nt][1];
                            __half h0 = __float2half_rn(a0), h1 = __float2half_rn(a1);
                            *(u32*)(bh + off) = (u32)__half_as_ushort(h0) | ((u32)__half_as_ushort(h1) << 16);
                            *(u32*)(bl + off) = packh(a0 - __half2float(h0), a1 - __half2float(h1));
                        }
                        {
                            int cc = rB >> 1, tl = rB & 1;
                            u32 off = (u32)((cc * BP + tl * 26 + n0) * 2);
                            float a0 = accm[nt][2], a1 = accm[nt][3];
                            __half h0 = __float2half_rn(a0), h1 = __float2half_rn(a1);
                            *(u32*)(bh + off) = (u32)__half_as_ushort(h0) | ((u32)__half_as_ushort(h1) << 16);
                            *(u32*)(bl + off) = packh(a0 - __half2float(h0), a1 - __half2float(h1));
                        }
                    }
                }
            }
            BAR_ARRIVE(BAR_FULL(buf), 512);
        }
    }
}

// ---------------- launch ----------------
extern "C" void kernel_launch(void* const* d_in, const int* in_sizes, int n_in,
                              void* d_out, int out_size) {
    const float* x     = (const float*)d_in[0];
    const float* adj   = (const float*)d_in[1];
    const float* Wk    = (const float*)d_in[2];
    const float* bk    = (const float*)d_in[3];
    const float* Wq    = (const float*)d_in[4];
    const float* bq    = (const float*)d_in[5];
    const float* Ws    = (const float*)d_in[6];
    const float* bs    = (const float*)d_in[7];
    const float* gamma = (const float*)d_in[8];
    const float* beta  = (const float*)d_in[9];
    const float* rmean = (const float*)d_in[10];
    const float* rvar  = (const float*)d_in[11];
    const float* alpha = (const float*)d_in[12];
    float* out = (float*)d_out;

    cudaFuncSetAttribute(k3_main, cudaFuncAttributeMaxDynamicSharedMemorySize, SMEM_TOTAL);

    k1_mean<<<dim3(8, NB), 256>>>(x);
    k2_attn<<<NB, 256>>>(adj, Wk, bk, Wq, bq, alpha);
    k3_main<<<dim3(TT / TSLAB, NB), 512, SMEM_TOTAL>>>(x, Ws, bs, gamma, beta, rmean, rvar, out);
}

// round 15
// speedup vs baseline: 1.9712x; 1.0091x over previous
#include <cuda_runtime.h>
#include <cuda_fp16.h>

typedef unsigned int u32;
typedef unsigned long long u64;

#define NB 64
#define CIN 128
#define COUT 128
#define TT 128
#define JJ 25

#define TSLAB 64            // t's per CTA -> 128 CTAs total, 1 wave
#define CHT 2
#define NCHUNK 32
#define NTILES 7
#define AP 136
#define BP 56
#define RAWP 52             // floats per raw row (50 data + 2 pad) -> 208B, 8B-aligned rows
#define XP 40

// ---- smem byte offsets ----
#define SM_CSF   0
#define SM_SBN   128
#define SM_E16H  2176
#define SM_E16L  4736
#define SM_A_HI  7296
#define SM_A_LO  42112
#define SM_B0    76928
#define B_HALF   14336
#define B_BUF    28672
#define SM_BH(b) (SM_B0 + (b)*B_BUF)
#define SM_BL(b) (SM_BH(b) + B_HALF)
#define SM_X_HI  134272
#define SM_X_LO  154752
#define SM_RAW0  175232
#define RAW_BYTES 26624                  // 128*52*4
#define SM_RAW(b) (SM_RAW0 + (b)*RAW_BYTES)
#define SMEM_TOTAL 228480

// named barrier ids
#define BAR_FULL(b) (1 + (b))
#define BAR_FREE(b) (3 + (b))
#define BAR_PROD    5
#define BAR_CONS    6

// ---------------- scratch ----------------
__device__ float g_xt_mean[NB * CIN * JJ];
__device__ float g_E[NB * JJ * JJ];
__device__ float g_csf[NB * JJ];

// ---------------- helpers ----------------
__device__ __forceinline__ u32 smem_u32(const void* p) {
    u32 a; asm("{ .reg .u64 t; cvta.to.shared.u64 t, %1; cvt.u32.u64 %0, t; }" : "=r"(a) : "l"(p));
    return a;
}
__device__ __forceinline__ void ldsm_x4(u32* r, u32 addr) {
    asm volatile("ldmatrix.sync.aligned.m8n8.x4.shared.b16 {%0,%1,%2,%3}, [%4];"
        : "=r"(r[0]), "=r"(r[1]), "=r"(r[2]), "=r"(r[3]) : "r"(addr) : "memory");
}
__device__ __forceinline__ void ldsm_x4t(u32* r, u32 addr) {
    asm volatile("ldmatrix.sync.aligned.m8n8.x4.trans.shared.b16 {%0,%1,%2,%3}, [%4];"
        : "=r"(r[0]), "=r"(r[1]), "=r"(r[2]), "=r"(r[3]) : "r"(addr) : "memory");
}
__device__ __forceinline__ void ldsm_x2t(u32* r, u32 addr) {
    asm volatile("ldmatrix.sync.aligned.m8n8.x2.trans.shared.b16 {%0,%1}, [%2];"
        : "=r"(r[0]), "=r"(r[1]) : "r"(addr) : "memory");
}
__device__ __forceinline__ void mma_fp16(float* d, const u32* a, const u32* b) {
    asm volatile("mma.sync.aligned.m16n8k16.row.col.f32.f16.f16.f32 "
        "{%0,%1,%2,%3}, {%4,%5,%6,%7}, {%8,%9}, {%0,%1,%2,%3};"
        : "+f"(d[0]), "+f"(d[1]), "+f"(d[2]), "+f"(d[3])
        : "r"(a[0]), "r"(a[1]), "r"(a[2]), "r"(a[3]), "r"(b[0]), "r"(b[1]));
}
__device__ __forceinline__ void cp8(u32 dst, const void* src) {
    asm volatile("cp.async.ca.shared.global [%0], [%1], 8;" :: "r"(dst), "l"(src) : "memory");
}
#define CP_COMMIT() asm volatile("cp.async.commit_group;" ::: "memory")
#define CP_WAIT1()  asm volatile("cp.async.wait_group 1;" ::: "memory")
#define CP_WAITALL() asm volatile("cp.async.wait_group 0;" ::: "memory")
#define BAR_SYNC(id, cnt) asm volatile("bar.sync %0, %1;" :: "r"(id), "r"(cnt) : "memory")
#define BAR_ARRIVE(id, cnt) asm volatile("bar.arrive %0, %1;" :: "r"(id), "r"(cnt) : "memory")

__device__ __forceinline__ u32 packh(float a, float b) {
    __half h0 = __float2half_rn(a), h1 = __float2half_rn(b);
    return (u32)__half_as_ushort(h0) | ((u32)__half_as_ushort(h1) << 16);
}

// ---------------- K1: temporal mean (2 channels x 8-deep unroll = 16 MLP) ----------------
__global__ void k1_mean(const float* __restrict__ x) {
    int b = blockIdx.y;
    int c0 = blockIdx.x * 16 + (threadIdx.x >> 5) * 2;
    int j = threadIdx.x & 31;
    if (j >= JJ) return;
    const float* p0 = x + ((size_t)(b * CIN + c0) * TT) * JJ + j;
    const float* p1 = p0 + (size_t)TT * JJ;
    float a0 = 0.f, a1 = 0.f, a2 = 0.f, a3 = 0.f;
    float a4 = 0.f, a5 = 0.f, a6 = 0.f, a7 = 0.f;
    float b0 = 0.f, b1 = 0.f, b2 = 0.f, b3 = 0.f;
    float b4 = 0.f, b5 = 0.f, b6 = 0.f, b7 = 0.f;
#pragma unroll 4
    for (int t = 0; t < TT; t += 8) {
        a0 += p0[t * JJ];       b0 += p1[t * JJ];
        a1 += p0[(t + 1) * JJ]; b1 += p1[(t + 1) * JJ];
        a2 += p0[(t + 2) * JJ]; b2 += p1[(t + 2) * JJ];
        a3 += p0[(t + 3) * JJ]; b3 += p1[(t + 3) * JJ];
        a4 += p0[(t + 4) * JJ]; b4 += p1[(t + 4) * JJ];
        a5 += p0[(t + 5) * JJ]; b5 += p1[(t + 5) * JJ];
        a6 += p0[(t + 6) * JJ]; b6 += p1[(t + 6) * JJ];
        a7 += p0[(t + 7) * JJ]; b7 += p1[(t + 7) * JJ];
    }
    g_xt_mean[(b * CIN + c0) * JJ + j] =
        (((a0 + a1) + (a2 + a3)) + ((a4 + a5) + (a6 + a7))) * (1.0f / TT);
    g_xt_mean[(b * CIN + c0 + 1) * JJ + j] =
        (((b0 + b1) + (b2 + b3)) + ((b4 + b5) + (b6 + b7))) * (1.0f / TT);
}

// ---------------- K2: per-batch attention (256 thr, j-split GEMV) ----------------
__global__ void k2_attn(const float* __restrict__ adj,
                        const float* __restrict__ Wk, const float* __restrict__ bk,
                        const float* __restrict__ Wq, const float* __restrict__ bq,
                        const float* __restrict__ alphaPtr) {
    int b = blockIdx.x;
    int tid = threadIdx.x;  // 256
    __shared__ float xt[CIN * 26];
    __shared__ float skk[COUT * 26];
    __shared__ float sqq[COUT * 26];
    __shared__ float sdyn[JJ * 26];

    for (int i = tid; i < CIN * JJ; i += 256) {
        int c = i / JJ, j = i - c * JJ;
        xt[c * 26 + j] = g_xt_mean[b * CIN * JJ + i];
    }
    __syncthreads();
    {
        int o = tid >> 1, half = tid & 1;
        int j0 = half * 13;
        int nj = half ? 12 : 13;
        const float4* wk4 = (const float4*)(Wk + o * CIN);
        const float4* wq4 = (const float4*)(Wq + o * CIN);
        float ak[13], aq[13];
#pragma unroll
        for (int jj = 0; jj < 13; ++jj) { ak[jj] = 0.f; aq[jj] = 0.f; }
#pragma unroll 4
        for (int c4 = 0; c4 < CIN / 4; ++c4) {
            float4 wk = wk4[c4], wq = wq4[c4];
            const float* x0 = &xt[(c4 * 4) * 26] + j0;
#pragma unroll
            for (int jj = 0; jj < 13; ++jj) {
                if (jj < nj) {
                    float v0 = x0[jj], v1 = x0[26 + jj], v2 = x0[52 + jj], v3 = x0[78 + jj];
                    float a = ak[jj], q = aq[jj];
                    a = fmaf(wk.x, v0, a); q = fmaf(wq.x, v0, q);
                    a = fmaf(wk.y, v1, a); q = fmaf(wq.y, v1, q);
                    a = fmaf(wk.z, v2, a); q = fmaf(wq.z, v2, q);
                    a = fmaf(wk.w, v3, a); q = fmaf(wq.w, v3, q);
                    ak[jj] = a; aq[jj] = q;
                }
            }
        }
        float bko = bk[o], bqo = bq[o];
#pragma unroll
        for (int jj = 0; jj < 13; ++jj)
            if (jj < nj) {
                skk[o * 26 + j0 + jj] = ak[jj] + bko;
                sqq[o * 26 + j0 + jj] = aq[jj] + bqo;
            }
    }
    __syncthreads();
    const float inv_scale = 0.08838834764831843f;  // 1/sqrt(128)
    for (int i = tid; i < JJ * JJ; i += 256) {
        int j = i / JJ, k = i - j * JJ;
        float acc = 0.f;
        for (int o = 0; o < COUT; o++) acc = fmaf(sqq[o * 26 + j], skk[o * 26 + k], acc);
        sdyn[j * 26 + k] = acc * inv_scale;
    }
    __syncthreads();
    if (tid < JJ) {
        int j = tid;
        float m = -1e30f;
#pragma unroll
        for (int k = 0; k < JJ; k++) m = fmaxf(m, sdyn[j * 26 + k]);
        float e[JJ]; float s = 0.f;
#pragma unroll
        for (int k = 0; k < JJ; k++) { e[k] = expf(sdyn[j * 26 + k] - m); s += e[k]; }
        float inv = 1.0f / s;
#pragma unroll
        for (int k = 0; k < JJ; k++) sdyn[j * 26 + k] = e[k] * inv;
    }
    __syncthreads();
    float alpha = alphaPtr[0];
    for (int i = tid; i < JJ * JJ; i += 256) {
        int j = i / JJ, k = i - j * JJ;
        float acc = 0.f;
#pragma unroll
        for (int m2 = 0; m2 < JJ; m2++) acc = fmaf(adj[j * JJ + m2], sdyn[m2 * 26 + k], acc);
        g_E[b * JJ * JJ + i] = adj[j * JJ + k] + alpha * acc;
    }
    if (tid < JJ) {
        int k = tid;
        float acc = 0.f;
#pragma unroll
        for (int j = 0; j < JJ; j++) acc += sdyn[j * 26 + k];
        g_csf[b * JJ + k] = 1.0f + alpha * acc;
    }
}

// raw chunk loader: 3200 cp8 (128 rows x 25), coalesced 8B
__device__ __forceinline__ void load_raw(u32 sbase, int buf, const float* __restrict__ xb,
                                         int ch, int ptid) {
#pragma unroll
    for (int i = 0; i < 13; ++i) {
        int flat = ptid + 256 * i;
        if (flat < 3200) {
            int c = flat / 25, w = flat - 25 * c;
            cp8(sbase + SM_RAW(buf) + (u32)((c * RAWP + w * 2) * 4),
                xb + (size_t)c * 3200 + ch * 50 + w * 2);
        }
    }
    CP_COMMIT();
}

// ---------------- K3 ----------------
__global__ void __launch_bounds__(512, 1)
k3_main(const float* __restrict__ x, const float* __restrict__ Ws,
        const float* __restrict__ bs, const float* __restrict__ gamma,
        const float* __restrict__ beta, const float* __restrict__ rmean,
        const float* __restrict__ rvar, float* __restrict__ out) {
    extern __shared__ char sm[];
    u32 sbase = smem_u32(sm);
    int tid = threadIdx.x;
    int b = blockIdx.y, slab = blockIdx.x;
    int t0slab = slab * TSLAB;

    bool is_prod = tid >= 256;
    int ptid = tid & 255;
    const float* xb = x + (size_t)b * 409600 + (size_t)t0slab * 25;

    // ---- producers: cp.async raw chunks 0,1 ----
    if (is_prod) {
        load_raw(sbase, 0, xb, 0, ptid);
        load_raw(sbase, 1, xb, 1, ptid);
    }

    // ---- staging (all 512 threads) ----
    float* csf = (float*)(sm + SM_CSF);
    if (tid < 32) csf[tid] = (tid < JJ) ? g_csf[b * JJ + tid] : 0.f;
    if (tid >= 32 && tid < 160) {
        int o = tid - 32;
        float inv = gamma[o] * rsqrtf(rvar[o] + 1e-5f);
        float sh = beta[o] - rmean[o] * inv;
        ((float4*)(sm + SM_SBN))[o] = make_float4(inv, sh, bs[o], 0.f);
    }
    {
        __half* eh = (__half*)(sm + SM_E16H);
        __half* el = (__half*)(sm + SM_E16L);
        for (int i = tid; i < 32 * XP; i += 512) {
            int j = i / XP, n = i - j * XP;
            float v = (j < JJ && n < JJ) ? g_E[b * 625 + j * 25 + n] : 0.f;
            __half h = __float2half_rn(v);
            eh[i] = h;
            el[i] = __float2half_rn(v - __half2float(h));
        }
    }
    {
        __half* ah = (__half*)(sm + SM_A_HI);
        __half* al = (__half*)(sm + SM_A_LO);
        for (int i = tid; i < COUT * CIN; i += 512) {
            int o = i >> 7, c = i & 127;
            float v = Ws[i];
            __half hb = __float2half_rn(v);
            ah[o * AP + c] = hb;
            al[o * AP + c] = __float2half_rn(v - __half2float(hb));
        }
    }
    __syncthreads();

    if (!is_prod) {
        // ===== CONSUMERS (warps 0..7): Ahi-resident pipelined GEMM + epilogue =====
        int warp = tid >> 5, lane = tid & 31;
        int o0 = warp * 16;
        int gid = lane >> 2, tig = lane & 3;
        u32 arow  = (u32)(o0 + (lane & 15));
        u32 acsel = (u32)((lane >> 4) * 8);
        u32 brow  = (u32)((lane & 7) + ((lane >> 3) & 1) * 8);
        u32 bcsel = (u32)((lane >> 4) * 8);
        u32 brow2 = (u32)(lane & 15);
        int o_a = o0 + gid, o_b = o_a + 8;
        float ck = csf[lane & 31];
        float* outb = out + (size_t)b * 409600;
        const float4* sbn = (const float4*)(sm + SM_SBN);

        u32 AbH = sbase + (u32)SM_A_HI + (arow * AP + acsel) * 2;
        u32 AbL = sbase + (u32)SM_A_LO + (arow * AP + acsel) * 2;

        u32 fahi[8][4];
#pragma unroll
        for (int kt = 0; kt < 8; ++kt) ldsm_x4(fahi[kt], AbH + (u32)(kt * 32));

        for (int ch = 0; ch < NCHUNK; ++ch) {
            int cbuf = ch & 1;
            BAR_SYNC(BAR_FULL(cbuf), 512);

            u32 BbH = sbase + (u32)SM_BH(cbuf);
            u32 BbL = sbase + (u32)SM_BL(cbuf);
            u32 BroH  = BbH + (brow * BP + bcsel) * 2;
            u32 BroL  = BbL + (brow * BP + bcsel) * 2;
            u32 Bro2H = BbH + (brow2 * BP + 48u) * 2;
            u32 Bro2L = BbL + (brow2 * BP + 48u) * 2;

            float acc[NTILES][4];
#pragma unroll
            for (int nt = 0; nt < NTILES; ++nt)
#pragma unroll
                for (int r = 0; r < 4; ++r) acc[nt][r] = 0.f;

            u32 bhi[2][14], blo[14], alo[4];
#define LDBHI(pb, kt) do {                                                  \
    u32 kb = (u32)((kt) * 16 * BP * 2);                                     \
    ldsm_x4t(&bhi[pb][0],  BroH + kb);                                      \
    ldsm_x4t(&bhi[pb][4],  BroH + kb + 32u);                                \
    ldsm_x4t(&bhi[pb][8],  BroH + kb + 64u);                                \
    ldsm_x2t(&bhi[pb][12], Bro2H + kb);                                     \
} while (0)
#define LDBLO(kt) do {                                                      \
    u32 kb = (u32)((kt) * 16 * BP * 2);                                     \
    ldsm_x4t(&blo[0],  BroL + kb);                                          \
    ldsm_x4t(&blo[4],  BroL + kb + 32u);                                    \
    ldsm_x4t(&blo[8],  BroL + kb + 64u);                                    \
    ldsm_x2t(&blo[12], Bro2L + kb);                                         \
} while (0)
            LDBHI(0, 0);
#pragma unroll
            for (int kt = 0; kt < 8; ++kt) {
                int pb = kt & 1;
                LDBLO(kt);
                ldsm_x4(alo, AbL + (u32)(kt * 32));
                mma_fp16(acc[0], fahi[kt], &bhi[pb][0]);
                mma_fp16(acc[1], fahi[kt], &bhi[pb][2]);
                mma_fp16(acc[2], fahi[kt], &bhi[pb][4]);
                mma_fp16(acc[3], fahi[kt], &bhi[pb][6]);
                mma_fp16(acc[4], fahi[kt], &bhi[pb][8]);
                mma_fp16(acc[5], fahi[kt], &bhi[pb][10]);
                mma_fp16(acc[6], fahi[kt], &bhi[pb][12]);
                if (kt < 7) LDBHI(pb ^ 1, kt + 1);
                mma_fp16(acc[0], alo, &bhi[pb][0]);
                mma_fp16(acc[1], alo, &bhi[pb][2]);
                mma_fp16(acc[2], alo, &bhi[pb][4]);
                mma_fp16(acc[3], alo, &bhi[pb][6]);
                mma_fp16(acc[4], alo, &bhi[pb][8]);
                mma_fp16(acc[5], alo, &bhi[pb][10]);
                mma_fp16(acc[6], alo, &bhi[pb][12]);
                mma_fp16(acc[0], fahi[kt], &blo[0]);
                mma_fp16(acc[1], fahi[kt], &blo[2]);
                mma_fp16(acc[2], fahi[kt], &blo[4]);
                mma_fp16(acc[3], fahi[kt], &blo[6]);
                mma_fp16(acc[4], fahi[kt], &blo[8]);
                mma_fp16(acc[5], fahi[kt], &blo[10]);
                mma_fp16(acc[6], fahi[kt], &blo[12]);
            }
#undef LDBHI
#undef LDBLO

            BAR_SYNC(BAR_CONS, 256);
            float* D = (float*)(sm + SM_BH(cbuf));
#pragma unroll
            for (int nt = 0; nt < NTILES; ++nt) {
                int n0 = nt * 8 + tig * 2;
                D[o_a * 56 + n0]     = acc[nt][0];
                D[o_a * 56 + n0 + 1] = acc[nt][1];
                D[o_b * 56 + n0]     = acc[nt][2];
                D[o_b * 56 + n0 + 1] = acc[nt][3];
            }
            BAR_SYNC(BAR_CONS, 256);

            int tch = t0slab + ch * CHT;
#pragma unroll
            for (int rr = 0; rr < 32; ++rr) {
                int idx = warp * 32 + rr;
                int o = idx >> 1, tl = idx & 1;
                float4 bn = sbn[o];
                if (lane < JJ) {
                    float v = D[o * 56 + tl * 26 + lane];
                    float pre = fmaf(bn.z, ck, v);
                    outb[(size_t)o * 3200 + (tch + tl) * 25 + lane] =
                        fmaxf(fmaf(pre, bn.x, bn.y), 0.f);
                }
            }
            BAR_ARRIVE(BAR_FREE(cbuf), 512);
        }
    } else {
        // ===== PRODUCERS (warps 8..15): cvt + mix-MMA =====
        int pw = (tid >> 5) - 8;
        int lane = tid & 31;
        int mbase = 32 * pw;
        u32 xrow  = (u32)(lane & 15);
        u32 xcsel = (u32)((lane >> 4) * 8);
        u32 erow  = (u32)((lane & 7) + ((lane >> 3) & 1) * 8);
        u32 ecsel = (u32)((lane >> 4) * 8);
        int r_cv = ptid, c_cv = r_cv >> 1, t_cv = r_cv & 1;

        for (int ch = 0; ch < NCHUNK; ++ch) {
            int buf = ch & 1;
            if (ch < NCHUNK - 2) { CP_WAIT1(); } else { CP_WAITALL(); }
            BAR_SYNC(BAR_PROD, 256);

            {
                const float* xr = (const float*)(sm + SM_RAW(buf)) + c_cv * RAWP + t_cv * 25;
#pragma unroll
                for (int s = 0; s < 4; ++s) {
                    u32 hi[4], lo[4];
#pragma unroll
                    for (int qq = 0; qq < 4; ++qq) {
                        int q = 4 * s + qq;
                        float f0 = (2 * q < 25) ? xr[2 * q] : 0.f;
                        float f1 = (2 * q + 1 < 25) ? xr[2 * q + 1] : 0.f;
                        __half h0 = __float2half_rn(f0), h1 = __float2half_rn(f1);
                        hi[qq] = (u32)__half_as_ushort(h0) | ((u32)__half_as_ushort(h1) << 16);
                        lo[qq] = packh(f0 - __half2float(h0), f1 - __half2float(h1));
                    }
                    *(uint4*)(sm + SM_X_HI + r_cv * 80 + s * 16) = make_uint4(hi[0], hi[1], hi[2], hi[3]);
                    *(uint4*)(sm + SM_X_LO + r_cv * 80 + s * 16) = make_uint4(lo[0], lo[1], lo[2], lo[3]);
                }
            }
            BAR_SYNC(BAR_PROD, 256);

            if (ch + 2 < NCHUNK) load_raw(sbase, buf, xb, ch + 2, ptid);

            if (ch >= 2) BAR_SYNC(BAR_FREE(buf), 512);

            char* bh = sm + SM_BH(buf);
            char* bl = sm + SM_BL(buf);
#pragma unroll
            for (int mt = 0; mt < 2; ++mt) {
                u32 ro = (u32)((mbase + mt * 16) + xrow);
                u32 xfH[2][4], xfL[2][4], ef[2][2][4];
                float accm[4][4];
#pragma unroll
                for (int nt = 0; nt < 4; ++nt)
#pragma unroll
                    for (int r = 0; r < 4; ++r) accm[nt][r] = 0.f;
#pragma unroll
                for (int kt = 0; kt < 2; ++kt) {
                    ldsm_x4(xfH[kt], sbase + (u32)SM_X_HI + (ro * XP + (u32)(kt * 16) + xcsel) * 2);
                    ldsm_x4(xfL[kt], sbase + (u32)SM_X_LO + (ro * XP + (u32)(kt * 16) + xcsel) * 2);
                }
#pragma unroll
                for (int kt = 0; kt < 2; ++kt)
#pragma unroll
                    for (int n2 = 0; n2 < 2; ++n2)
                        ldsm_x4t(ef[kt][n2], sbase + (u32)SM_E16H +
                                 (((u32)(kt * 16) + erow) * XP + (u32)(n2 * 16) + ecsel) * 2);
#pragma unroll
                for (int kt = 0; kt < 2; ++kt)
#pragma unroll
                    for (int n2 = 0; n2 < 2; ++n2) {
                        mma_fp16(accm[2 * n2],     xfH[kt], ef[kt][n2]);
                        mma_fp16(accm[2 * n2 + 1], xfH[kt], ef[kt][n2] + 2);
                        mma_fp16(accm[2 * n2],     xfL[kt], ef[kt][n2]);
                        mma_fp16(accm[2 * n2 + 1], xfL[kt], ef[kt][n2] + 2);
                    }
#pragma unroll
                for (int kt = 0; kt < 2; ++kt)
#pragma unroll
                    for (int n2 = 0; n2 < 2; ++n2)
                        ldsm_x4t(ef[kt][n2], sbase + (u32)SM_E16L +
                                 (((u32)(kt * 16) + erow) * XP + (u32)(n2 * 16) + ecsel) * 2);
#pragma unroll
                for (int kt = 0; kt < 2; ++kt)
#pragma unroll
                    for (int n2 = 0; n2 < 2; ++n2) {
                        mma_fp16(accm[2 * n2],     xfH[kt], ef[kt][n2]);
                        mma_fp16(accm[2 * n2 + 1], xfH[kt], ef[kt][n2] + 2);
                    }

#pragma unroll
                for (int nt = 0; nt < 4; ++nt) {
                    int n0 = nt * 8 + (lane & 3) * 2;
                    if (n0 < 26) {
                        int rA = mbase + mt * 16 + (lane >> 2);
                        int rB = rA + 8;
                        {
                            int cc = rA >> 1, tl = rA & 1;
                            u32 off = (u32)((cc * BP + tl * 26 + n0) * 2);
                            float a0 = accm[nt][0], a1 = accm[nt][1];
                            __half h0 = __float2half_rn(a0), h1 = __float2half_rn(a1);
                            *(u32*)(bh + off) = (u32)__half_as_ushort(h0) | ((u32)__half_as_ushort(h1) << 16);
                            *(u32*)(bl + off) = packh(a0 - __half2float(h0), a1 - __half2float(h1));
                        }
                        {
                            int cc = rB >> 1, tl = rB & 1;
                            u32 off = (u32)((cc * BP + tl * 26 + n0) * 2);
                            float a0 = accm[nt][2], a1 = accm[nt][3];
                            __half h0 = __float2half_rn(a0), h1 = __float2half_rn(a1);
                            *(u32*)(bh + off) = (u32)__half_as_ushort(h0) | ((u32)__half_as_ushort(h1) << 16);
                            *(u32*)(bl + off) = packh(a0 - __half2float(h0), a1 - __half2float(h1));
                        }
                    }
                }
            }
            BAR_ARRIVE(BAR_FULL(buf), 512);
        }
    }
}

// ---------------- launch ----------------
extern "C" void kernel_launch(void* const* d_in, const int* in_sizes, int n_in,
                              void* d_out, int out_size) {
    const float* x     = (const float*)d_in[0];
    const float* adj   = (const float*)d_in[1];
    const float* Wk    = (const float*)d_in[2];
    const float* bk    = (const float*)d_in[3];
    const float* Wq    = (const float*)d_in[4];
    const float* bq    = (const float*)d_in[5];
    const float* Ws    = (const float*)d_in[6];
    const float* bs    = (const float*)d_in[7];
    const float* gamma = (const float*)d_in[8];
    const float* beta  = (const float*)d_in[9];
    const float* rmean = (const float*)d_in[10];
    const float* rvar  = (const float*)d_in[11];
    const float* alpha = (const float*)d_in[12];
    float* out = (float*)d_out;

    cudaFuncSetAttribute(k3_main, cudaFuncAttributeMaxDynamicSharedMemorySize, SMEM_TOTAL);

    k1_mean<<<dim3(8, NB), 256>>>(x);
    k2_attn<<<NB, 256>>>(adj, Wk, bk, Wq, bq, alpha);
    k3_main<<<dim3(TT / TSLAB, NB), 512, SMEM_TOTAL>>>(x, Ws, bs, gamma, beta, rmean, rvar, out);
}

// round 16
// speedup vs baseline: 2.0169x; 1.0232x over previous
#include <cuda_runtime.h>
#include <cuda_fp16.h>

typedef unsigned int u32;
typedef unsigned long long u64;

#define NB 64
#define CIN 128
#define COUT 128
#define TT 128
#define JJ 25

#define TSLAB 64            // t's per CTA -> 128 CTAs total, 1 wave
#define CHT 2
#define NCHUNK 32
#define NTILES 7
#define AP 136
#define BP 56
#define RAWP 52             // floats per raw row (50 data + 2 pad) -> 208B, 8B-aligned rows
#define XP 40

// ---- smem byte offsets ----
#define SM_CSF   0
#define SM_SBN   128
#define SM_E16H  2176
#define SM_E16L  4736
#define SM_A_HI  7296
#define SM_A_LO  42112
#define SM_B0    76928
#define B_HALF   14336
#define B_BUF    28672
#define SM_BH(b) (SM_B0 + (b)*B_BUF)
#define SM_BL(b) (SM_BH(b) + B_HALF)
#define SM_X_HI  134272
#define SM_X_LO  154752
#define SM_RAW0  175232
#define RAW_BYTES 26624                  // 128*52*4
#define SM_RAW(b) (SM_RAW0 + (b)*RAW_BYTES)
#define SMEM_TOTAL 228480

// named barrier ids
#define BAR_FULL(b) (1 + (b))
#define BAR_FREE(b) (3 + (b))
#define BAR_PROD    5
#define BAR_CONS    6

// ---------------- scratch ----------------
__device__ float g_xt_mean[NB * CIN * JJ];
__device__ float g_E[NB * JJ * JJ];
__device__ float g_csf[NB * JJ];

// ---------------- helpers ----------------
__device__ __forceinline__ u32 smem_u32(const void* p) {
    u32 a; asm("{ .reg .u64 t; cvta.to.shared.u64 t, %1; cvt.u32.u64 %0, t; }" : "=r"(a) : "l"(p));
    return a;
}
__device__ __forceinline__ void ldsm_x4(u32* r, u32 addr) {
    asm volatile("ldmatrix.sync.aligned.m8n8.x4.shared.b16 {%0,%1,%2,%3}, [%4];"
        : "=r"(r[0]), "=r"(r[1]), "=r"(r[2]), "=r"(r[3]) : "r"(addr) : "memory");
}
__device__ __forceinline__ void ldsm_x4t(u32* r, u32 addr) {
    asm volatile("ldmatrix.sync.aligned.m8n8.x4.trans.shared.b16 {%0,%1,%2,%3}, [%4];"
        : "=r"(r[0]), "=r"(r[1]), "=r"(r[2]), "=r"(r[3]) : "r"(addr) : "memory");
}
__device__ __forceinline__ void ldsm_x2t(u32* r, u32 addr) {
    asm volatile("ldmatrix.sync.aligned.m8n8.x2.trans.shared.b16 {%0,%1}, [%2];"
        : "=r"(r[0]), "=r"(r[1]) : "r"(addr) : "memory");
}
__device__ __forceinline__ void mma_fp16(float* d, const u32* a, const u32* b) {
    asm volatile("mma.sync.aligned.m16n8k16.row.col.f32.f16.f16.f32 "
        "{%0,%1,%2,%3}, {%4,%5,%6,%7}, {%8,%9}, {%0,%1,%2,%3};"
        : "+f"(d[0]), "+f"(d[1]), "+f"(d[2]), "+f"(d[3])
        : "r"(a[0]), "r"(a[1]), "r"(a[2]), "r"(a[3]), "r"(b[0]), "r"(b[1]));
}
__device__ __forceinline__ void cp8(u32 dst, const void* src) {
    asm volatile("cp.async.ca.shared.global [%0], [%1], 8;" :: "r"(dst), "l"(src) : "memory");
}
#define CP_COMMIT() asm volatile("cp.async.commit_group;" ::: "memory")
#define CP_WAIT1()  asm volatile("cp.async.wait_group 1;" ::: "memory")
#define CP_WAITALL() asm volatile("cp.async.wait_group 0;" ::: "memory")
#define BAR_SYNC(id, cnt) asm volatile("bar.sync %0, %1;" :: "r"(id), "r"(cnt) : "memory")
#define BAR_ARRIVE(id, cnt) asm volatile("bar.arrive %0, %1;" :: "r"(id), "r"(cnt) : "memory")

__device__ __forceinline__ u32 packh(float a, float b) {
    __half h0 = __float2half_rn(a), h1 = __float2half_rn(b);
    return (u32)__half_as_ushort(h0) | ((u32)__half_as_ushort(h1) << 16);
}

// ---------------- K1: temporal mean (round-14 exact: 2 ch/warp, unroll 8 x step 4) ----------------
__global__ void k1_mean(const float* __restrict__ x) {
    int b = blockIdx.y;
    int c0 = blockIdx.x * 16 + (threadIdx.x >> 5) * 2;
    int j = threadIdx.x & 31;
    if (j >= JJ) return;
    const float* p0 = x + ((size_t)(b * CIN + c0) * TT) * JJ + j;
    const float* p1 = p0 + (size_t)TT * JJ;
    float a0 = 0.f, a1 = 0.f, a2 = 0.f, a3 = 0.f;
    float b0 = 0.f, b1 = 0.f, b2 = 0.f, b3 = 0.f;
#pragma unroll 8
    for (int t = 0; t < TT; t += 4) {
        a0 += p0[t * JJ];       b0 += p1[t * JJ];
        a1 += p0[(t + 1) * JJ]; b1 += p1[(t + 1) * JJ];
        a2 += p0[(t + 2) * JJ]; b2 += p1[(t + 2) * JJ];
        a3 += p0[(t + 3) * JJ]; b3 += p1[(t + 3) * JJ];
    }
    g_xt_mean[(b * CIN + c0) * JJ + j]     = ((a0 + a1) + (a2 + a3)) * (1.0f / TT);
    g_xt_mean[(b * CIN + c0 + 1) * JJ + j] = ((b0 + b1) + (b2 + b3)) * (1.0f / TT);
}

// ---------------- K2: per-batch attention (256 thr, j-split GEMV) ----------------
__global__ void k2_attn(const float* __restrict__ adj,
                        const float* __restrict__ Wk, const float* __restrict__ bk,
                        const float* __restrict__ Wq, const float* __restrict__ bq,
                        const float* __restrict__ alphaPtr) {
    int b = blockIdx.x;
    int tid = threadIdx.x;  // 256
    __shared__ float xt[CIN * 26];
    __shared__ float skk[COUT * 26];
    __shared__ float sqq[COUT * 26];
    __shared__ float sdyn[JJ * 26];

    for (int i = tid; i < CIN * JJ; i += 256) {
        int c = i / JJ, j = i - c * JJ;
        xt[c * 26 + j] = g_xt_mean[b * CIN * JJ + i];
    }
    __syncthreads();
    {
        int o = tid >> 1, half = tid & 1;
        int j0 = half * 13;
        int nj = half ? 12 : 13;
        const float4* wk4 = (const float4*)(Wk + o * CIN);
        const float4* wq4 = (const float4*)(Wq + o * CIN);
        float ak[13], aq[13];
#pragma unroll
        for (int jj = 0; jj < 13; ++jj) { ak[jj] = 0.f; aq[jj] = 0.f; }
#pragma unroll 4
        for (int c4 = 0; c4 < CIN / 4; ++c4) {
            float4 wk = wk4[c4], wq = wq4[c4];
            const float* x0 = &xt[(c4 * 4) * 26] + j0;
#pragma unroll
            for (int jj = 0; jj < 13; ++jj) {
                if (jj < nj) {
                    float v0 = x0[jj], v1 = x0[26 + jj], v2 = x0[52 + jj], v3 = x0[78 + jj];
                    float a = ak[jj], q = aq[jj];
                    a = fmaf(wk.x, v0, a); q = fmaf(wq.x, v0, q);
                    a = fmaf(wk.y, v1, a); q = fmaf(wq.y, v1, q);
                    a = fmaf(wk.z, v2, a); q = fmaf(wq.z, v2, q);
                    a = fmaf(wk.w, v3, a); q = fmaf(wq.w, v3, q);
                    ak[jj] = a; aq[jj] = q;
                }
            }
        }
        float bko = bk[o], bqo = bq[o];
#pragma unroll
        for (int jj = 0; jj < 13; ++jj)
            if (jj < nj) {
                skk[o * 26 + j0 + jj] = ak[jj] + bko;
                sqq[o * 26 + j0 + jj] = aq[jj] + bqo;
            }
    }
    __syncthreads();
    const float inv_scale = 0.08838834764831843f;  // 1/sqrt(128)
    for (int i = tid; i < JJ * JJ; i += 256) {
        int j = i / JJ, k = i - j * JJ;
        float acc = 0.f;
        for (int o = 0; o < COUT; o++) acc = fmaf(sqq[o * 26 + j], skk[o * 26 + k], acc);
        sdyn[j * 26 + k] = acc * inv_scale;
    }
    __syncthreads();
    if (tid < JJ) {
        int j = tid;
        float m = -1e30f;
#pragma unroll
        for (int k = 0; k < JJ; k++) m = fmaxf(m, sdyn[j * 26 + k]);
        float e[JJ]; float s = 0.f;
#pragma unroll
        for (int k = 0; k < JJ; k++) { e[k] = expf(sdyn[j * 26 + k] - m); s += e[k]; }
        float inv = 1.0f / s;
#pragma unroll
        for (int k = 0; k < JJ; k++) sdyn[j * 26 + k] = e[k] * inv;
    }
    __syncthreads();
    float alpha = alphaPtr[0];
    for (int i = tid; i < JJ * JJ; i += 256) {
        int j = i / JJ, k = i - j * JJ;
        float acc = 0.f;
#pragma unroll
        for (int m2 = 0; m2 < JJ; m2++) acc = fmaf(adj[j * JJ + m2], sdyn[m2 * 26 + k], acc);
        g_E[b * JJ * JJ + i] = adj[j * JJ + k] + alpha * acc;
    }
    if (tid < JJ) {
        int k = tid;
        float acc = 0.f;
#pragma unroll
        for (int j = 0; j < JJ; j++) acc += sdyn[j * 26 + k];
        g_csf[b * JJ + k] = 1.0f + alpha * acc;
    }
}

// raw chunk loader: 3200 cp8 (128 rows x 25), coalesced 8B
__device__ __forceinline__ void load_raw(u32 sbase, int buf, const float* __restrict__ xb,
                                         int ch, int ptid) {
#pragma unroll
    for (int i = 0; i < 13; ++i) {
        int flat = ptid + 256 * i;
        if (flat < 3200) {
            int c = flat / 25, w = flat - 25 * c;
            cp8(sbase + SM_RAW(buf) + (u32)((c * RAWP + w * 2) * 4),
                xb + (size_t)c * 3200 + ch * 50 + w * 2);
        }
    }
    CP_COMMIT();
}

// ---------------- K3 ----------------
__global__ void __launch_bounds__(512, 1)
k3_main(const float* __restrict__ x, const float* __restrict__ Ws,
        const float* __restrict__ bs, const float* __restrict__ gamma,
        const float* __restrict__ beta, const float* __restrict__ rmean,
        const float* __restrict__ rvar, float* __restrict__ out) {
    extern __shared__ char sm[];
    u32 sbase = smem_u32(sm);
    int tid = threadIdx.x;
    int b = blockIdx.y, slab = blockIdx.x;
    int t0slab = slab * TSLAB;

    bool is_prod = tid >= 256;
    int ptid = tid & 255;
    const float* xb = x + (size_t)b * 409600 + (size_t)t0slab * 25;

    // ---- producers: cp.async raw chunks 0,1 ----
    if (is_prod) {
        load_raw(sbase, 0, xb, 0, ptid);
        load_raw(sbase, 1, xb, 1, ptid);
    }

    // ---- staging (all 512 threads) ----
    float* csf = (float*)(sm + SM_CSF);
    if (tid < 32) csf[tid] = (tid < JJ) ? g_csf[b * JJ + tid] : 0.f;
    if (tid >= 32 && tid < 160) {
        int o = tid - 32;
        float inv = gamma[o] * rsqrtf(rvar[o] + 1e-5f);
        float sh = beta[o] - rmean[o] * inv;
        ((float4*)(sm + SM_SBN))[o] = make_float4(inv, sh, bs[o], 0.f);
    }
    {
        __half* eh = (__half*)(sm + SM_E16H);
        __half* el = (__half*)(sm + SM_E16L);
        for (int i = tid; i < 32 * XP; i += 512) {
            int j = i / XP, n = i - j * XP;
            float v = (j < JJ && n < JJ) ? g_E[b * 625 + j * 25 + n] : 0.f;
            __half h = __float2half_rn(v);
            eh[i] = h;
            el[i] = __float2half_rn(v - __half2float(h));
        }
    }
    {
        __half* ah = (__half*)(sm + SM_A_HI);
        __half* al = (__half*)(sm + SM_A_LO);
        for (int i = tid; i < COUT * CIN; i += 512) {
            int o = i >> 7, c = i & 127;
            float v = Ws[i];
            __half hb = __float2half_rn(v);
            ah[o * AP + c] = hb;
            al[o * AP + c] = __float2half_rn(v - __half2float(hb));
        }
    }
    __syncthreads();

    if (!is_prod) {
        // ===== CONSUMERS (warps 0..7): Ahi-resident pipelined GEMM + epilogue =====
        int warp = tid >> 5, lane = tid & 31;
        int o0 = warp * 16;
        int gid = lane >> 2, tig = lane & 3;
        u32 arow  = (u32)(o0 + (lane & 15));
        u32 acsel = (u32)((lane >> 4) * 8);
        u32 brow  = (u32)((lane & 7) + ((lane >> 3) & 1) * 8);
        u32 bcsel = (u32)((lane >> 4) * 8);
        u32 brow2 = (u32)(lane & 15);
        int o_a = o0 + gid, o_b = o_a + 8;
        float ck = csf[lane & 31];
        float* outb = out + (size_t)b * 409600;
        const float4* sbn = (const float4*)(sm + SM_SBN);

        u32 AbH = sbase + (u32)SM_A_HI + (arow * AP + acsel) * 2;
        u32 AbL = sbase + (u32)SM_A_LO + (arow * AP + acsel) * 2;

        u32 fahi[8][4];
#pragma unroll
        for (int kt = 0; kt < 8; ++kt) ldsm_x4(fahi[kt], AbH + (u32)(kt * 32));

        for (int ch = 0; ch < NCHUNK; ++ch) {
            int cbuf = ch & 1;
            BAR_SYNC(BAR_FULL(cbuf), 512);

            u32 BbH = sbase + (u32)SM_BH(cbuf);
            u32 BbL = sbase + (u32)SM_BL(cbuf);
            u32 BroH  = BbH + (brow * BP + bcsel) * 2;
            u32 BroL  = BbL + (brow * BP + bcsel) * 2;
            u32 Bro2H = BbH + (brow2 * BP + 48u) * 2;
            u32 Bro2L = BbL + (brow2 * BP + 48u) * 2;

            float acc[NTILES][4];
#pragma unroll
            for (int nt = 0; nt < NTILES; ++nt)
#pragma unroll
                for (int r = 0; r < 4; ++r) acc[nt][r] = 0.f;

            u32 bhi[2][14], blo[14], alo[4];
#define LDBHI(pb, kt) do {                                                  \
    u32 kb = (u32)((kt) * 16 * BP * 2);                                     \
    ldsm_x4t(&bhi[pb][0],  BroH + kb);                                      \
    ldsm_x4t(&bhi[pb][4],  BroH + kb + 32u);                                \
    ldsm_x4t(&bhi[pb][8],  BroH + kb + 64u);                                \
    ldsm_x2t(&bhi[pb][12], Bro2H + kb);                                     \
} while (0)
#define LDBLO(kt) do {                                                      \
    u32 kb = (u32)((kt) * 16 * BP * 2);                                     \
    ldsm_x4t(&blo[0],  BroL + kb);                                          \
    ldsm_x4t(&blo[4],  BroL + kb + 32u);                                    \
    ldsm_x4t(&blo[8],  BroL + kb + 64u);                                    \
    ldsm_x2t(&blo[12], Bro2L + kb);                                         \
} while (0)
            LDBHI(0, 0);
#pragma unroll
            for (int kt = 0; kt < 8; ++kt) {
                int pb = kt & 1;
                LDBLO(kt);
                ldsm_x4(alo, AbL + (u32)(kt * 32));
                mma_fp16(acc[0], fahi[kt], &bhi[pb][0]);
                mma_fp16(acc[1], fahi[kt], &bhi[pb][2]);
                mma_fp16(acc[2], fahi[kt], &bhi[pb][4]);
                mma_fp16(acc[3], fahi[kt], &bhi[pb][6]);
                mma_fp16(acc[4], fahi[kt], &bhi[pb][8]);
                mma_fp16(acc[5], fahi[kt], &bhi[pb][10]);
                mma_fp16(acc[6], fahi[kt], &bhi[pb][12]);
                if (kt < 7) LDBHI(pb ^ 1, kt + 1);
                mma_fp16(acc[0], alo, &bhi[pb][0]);
                mma_fp16(acc[1], alo, &bhi[pb][2]);
                mma_fp16(acc[2], alo, &bhi[pb][4]);
                mma_fp16(acc[3], alo, &bhi[pb][6]);
                mma_fp16(acc[4], alo, &bhi[pb][8]);
                mma_fp16(acc[5], alo, &bhi[pb][10]);
                mma_fp16(acc[6], alo, &bhi[pb][12]);
                mma_fp16(acc[0], fahi[kt], &blo[0]);
                mma_fp16(acc[1], fahi[kt], &blo[2]);
                mma_fp16(acc[2], fahi[kt], &blo[4]);
                mma_fp16(acc[3], fahi[kt], &blo[6]);
                mma_fp16(acc[4], fahi[kt], &blo[8]);
                mma_fp16(acc[5], fahi[kt], &blo[10]);
                mma_fp16(acc[6], fahi[kt], &blo[12]);
            }
#undef LDBHI
#undef LDBLO

            BAR_SYNC(BAR_CONS, 256);
            float* D = (float*)(sm + SM_BH(cbuf));
#pragma unroll
            for (int nt = 0; nt < NTILES; ++nt) {
                int n0 = nt * 8 + tig * 2;
                D[o_a * 56 + n0]     = acc[nt][0];
                D[o_a * 56 + n0 + 1] = acc[nt][1];
                D[o_b * 56 + n0]     = acc[nt][2];
                D[o_b * 56 + n0 + 1] = acc[nt][3];
            }
            BAR_SYNC(BAR_CONS, 256);

            int tch = t0slab + ch * CHT;
#pragma unroll
            for (int rr = 0; rr < 32; ++rr) {
                int idx = warp * 32 + rr;
                int o = idx >> 1, tl = idx & 1;
                float4 bn = sbn[o];
                if (lane < JJ) {
                    float v = D[o * 56 + tl * 26 + lane];
                    float pre = fmaf(bn.z, ck, v);
                    outb[(size_t)o * 3200 + (tch + tl) * 25 + lane] =
                        fmaxf(fmaf(pre, bn.x, bn.y), 0.f);
                }
            }
            BAR_ARRIVE(BAR_FREE(cbuf), 512);
        }
    } else {
        // ===== PRODUCERS (warps 8..15): cvt + mix-MMA =====
        int pw = (tid >> 5) - 8;
        int lane = tid & 31;
        int mbase = 32 * pw;
        u32 xrow  = (u32)(lane & 15);
        u32 xcsel = (u32)((lane >> 4) * 8);
        u32 erow  = (u32)((lane & 7) + ((lane >> 3) & 1) * 8);
        u32 ecsel = (u32)((lane >> 4) * 8);
        int r_cv = ptid, c_cv = r_cv >> 1, t_cv = r_cv & 1;

        for (int ch = 0; ch < NCHUNK; ++ch) {
            int buf = ch & 1;
            if (ch < NCHUNK - 2) { CP_WAIT1(); } else { CP_WAITALL(); }
            BAR_SYNC(BAR_PROD, 256);

            {
                const float* xr = (const float*)(sm + SM_RAW(buf)) + c_cv * RAWP + t_cv * 25;
#pragma unroll
                for (int s = 0; s < 4; ++s) {
                    u32 hi[4], lo[4];
#pragma unroll
                    for (int qq = 0; qq < 4; ++qq) {
                        int q = 4 * s + qq;
                        float f0 = (2 * q < 25) ? xr[2 * q] : 0.f;
                        float f1 = (2 * q + 1 < 25) ? xr[2 * q + 1] : 0.f;
                        __half h0 = __float2half_rn(f0), h1 = __float2half_rn(f1);
                        hi[qq] = (u32)__half_as_ushort(h0) | ((u32)__half_as_ushort(h1) << 16);
                        lo[qq] = packh(f0 - __half2float(h0), f1 - __half2float(h1));
                    }
                    *(uint4*)(sm + SM_X_HI + r_cv * 80 + s * 16) = make_uint4(hi[0], hi[1], hi[2], hi[3]);
                    *(uint4*)(sm + SM_X_LO + r_cv * 80 + s * 16) = make_uint4(lo[0], lo[1], lo[2], lo[3]);
                }
            }
            BAR_SYNC(BAR_PROD, 256);

            if (ch + 2 < NCHUNK) load_raw(sbase, buf, xb, ch + 2, ptid);

            if (ch >= 2) BAR_SYNC(BAR_FREE(buf), 512);

            char* bh = sm + SM_BH(buf);
            char* bl = sm + SM_BL(buf);
#pragma unroll
            for (int mt = 0; mt < 2; ++mt) {
                u32 ro = (u32)((mbase + mt * 16) + xrow);
                u32 xfH[2][4], xfL[2][4], ef[2][2][4];
                float accm[4][4];
#pragma unroll
                for (int nt = 0; nt < 4; ++nt)
#pragma unroll
                    for (int r = 0; r < 4; ++r) accm[nt][r] = 0.f;
#pragma unroll
                for (int kt = 0; kt < 2; ++kt) {
                    ldsm_x4(xfH[kt], sbase + (u32)SM_X_HI + (ro * XP + (u32)(kt * 16) + xcsel) * 2);
                    ldsm_x4(xfL[kt], sbase + (u32)SM_X_LO + (ro * XP + (u32)(kt * 16) + xcsel) * 2);
                }
#pragma unroll
                for (int kt = 0; kt < 2; ++kt)
#pragma unroll
                    for (int n2 = 0; n2 < 2; ++n2)
                        ldsm_x4t(ef[kt][n2], sbase + (u32)SM_E16H +
                                 (((u32)(kt * 16) + erow) * XP + (u32)(n2 * 16) + ecsel) * 2);
#pragma unroll
                for (int kt = 0; kt < 2; ++kt)
#pragma unroll
                    for (int n2 = 0; n2 < 2; ++n2) {
                        mma_fp16(accm[2 * n2],     xfH[kt], ef[kt][n2]);
                        mma_fp16(accm[2 * n2 + 1], xfH[kt], ef[kt][n2] + 2);
                        mma_fp16(accm[2 * n2],     xfL[kt], ef[kt][n2]);
                        mma_fp16(accm[2 * n2 + 1], xfL[kt], ef[kt][n2] + 2);
                    }
#pragma unroll
                for (int kt = 0; kt < 2; ++kt)
#pragma unroll
                    for (int n2 = 0; n2 < 2; ++n2)
                        ldsm_x4t(ef[kt][n2], sbase + (u32)SM_E16L +
                                 (((u32)(kt * 16) + erow) * XP + (u32)(n2 * 16) + ecsel) * 2);
#pragma unroll
                for (int kt = 0; kt < 2; ++kt)
#pragma unroll
                    for (int n2 = 0; n2 < 2; ++n2) {
                        mma_fp16(accm[2 * n2],     xfH[kt], ef[kt][n2]);
                        mma_fp16(accm[2 * n2 + 1], xfH[kt], ef[kt][n2] + 2);
                    }

#pragma unroll
                for (int nt = 0; nt < 4; ++nt) {
                    int n0 = nt * 8 + (lane & 3) * 2;
                    if (n0 < 26) {
                        int rA = mbase + mt * 16 + (lane >> 2);
                        int rB = rA + 8;
                        {
                            int cc = rA >> 1, tl = rA & 1;
                            u32 off = (u32)((cc * BP + tl * 26 + n0) * 2);
                            float a0 = accm[nt][0], a1 = accm[nt][1];
                            __half h0 = __float2half_rn(a0), h1 = __float2half_rn(a1);
                            *(u32*)(bh + off) = (u32)__half_as_ushort(h0) | ((u32)__half_as_ushort(h1) << 16);
                            *(u32*)(bl + off) = packh(a0 - __half2float(h0), a1 - __half2float(h1));
                        }
                        {
                            int cc = rB >> 1, tl = rB & 1;
                            u32 off = (u32)((cc * BP + tl * 26 + n0) * 2);
                            float a0 = accm[nt][2], a1 = accm[nt][3];
                            __half h0 = __float2half_rn(a0), h1 = __float2half_rn(a1);
                            *(u32*)(bh + off) = (u32)__half_as_ushort(h0) | ((u32)__half_as_ushort(h1) << 16);
                            *(u32*)(bl + off) = packh(a0 - __half2float(h0), a1 - __half2float(h1));
                        }
                    }
                }
            }
            BAR_ARRIVE(BAR_FULL(buf), 512);
        }
    }
}

// ---------------- launch ----------------
extern "C" void kernel_launch(void* const* d_in, const int* in_sizes, int n_in,
                              void* d_out, int out_size) {
    const float* x     = (const float*)d_in[0];
    const float* adj   = (const float*)d_in[1];
    const float* Wk    = (const float*)d_in[2];
    const float* bk    = (const float*)d_in[3];
    const float* Wq    = (const float*)d_in[4];
    const float* bq    = (const float*)d_in[5];
    const float* Ws    = (const float*)d_in[6];
    const float* bs    = (const float*)d_in[7];
    const float* gamma = (const float*)d_in[8];
    const float* beta  = (const float*)d_in[9];
    const float* rmean = (const float*)d_in[10];
    const float* rvar  = (const float*)d_in[11];
    const float* alpha = (const float*)d_in[12];
    float* out = (float*)d_out;

    cudaFuncSetAttribute(k3_main, cudaFuncAttributeMaxDynamicSharedMemorySize, SMEM_TOTAL);

    k1_mean<<<dim3(8, NB), 256>>>(x);
    k2_attn<<<NB, 256>>>(adj, Wk, bk, Wq, bq, alpha);
    k3_main<<<dim3(TT / TSLAB, NB), 512, SMEM_TOTAL>>>(x, Ws, bs, gamma, beta, rmean, rvar, out);
}

// round 17
// speedup vs baseline: 2.0613x; 1.0220x over previous
#include <cuda_runtime.h>
#include <cuda_fp16.h>

typedef unsigned int u32;
typedef unsigned long long u64;

#define NB 64
#define CIN 128
#define COUT 128
#define TT 128
#define JJ 25

#define TSLAB 64            // t's per CTA -> 128 CTAs total, 1 wave
#define CHT 2
#define NCHUNK 32
#define NTILES 7
#define AP 136
#define BP 56
#define RAWP 52             // floats per raw row (50 data + 2 pad) -> 208B, 8B-aligned rows
#define XP 40

// ---- smem byte offsets ----
#define SM_CSF   0
#define SM_SBN   128
#define SM_E16H  2176
#define SM_E16L  4736
#define SM_A_HI  7296
#define SM_A_LO  42112
#define SM_B0    76928
#define B_HALF   14336
#define B_BUF    28672
#define SM_BH(b) (SM_B0 + (b)*B_BUF)
#define SM_BL(b) (SM_BH(b) + B_HALF)
#define SM_X_HI  134272
#define SM_X_LO  154752
#define SM_RAW0  175232
#define RAW_BYTES 26624                  // 128*52*4
#define SM_RAW(b) (SM_RAW0 + (b)*RAW_BYTES)
#define SMEM_TOTAL 228480

#define K1_SMEM 102400                   // 8 ch * 3200 floats

// named barrier ids
#define BAR_FULL(b) (1 + (b))
#define BAR_FREE(b) (3 + (b))
#define BAR_PROD    5
#define BAR_CONS    6

// ---------------- scratch ----------------
__device__ float g_xt_mean[NB * CIN * JJ];
__device__ float g_E[NB * JJ * JJ];
__device__ float g_csf[NB * JJ];

// ---------------- helpers ----------------
__device__ __forceinline__ u32 smem_u32(const void* p) {
    u32 a; asm("{ .reg .u64 t; cvta.to.shared.u64 t, %1; cvt.u32.u64 %0, t; }" : "=r"(a) : "l"(p));
    return a;
}
__device__ __forceinline__ void ldsm_x4(u32* r, u32 addr) {
    asm volatile("ldmatrix.sync.aligned.m8n8.x4.shared.b16 {%0,%1,%2,%3}, [%4];"
        : "=r"(r[0]), "=r"(r[1]), "=r"(r[2]), "=r"(r[3]) : "r"(addr) : "memory");
}
__device__ __forceinline__ void ldsm_x4t(u32* r, u32 addr) {
    asm volatile("ldmatrix.sync.aligned.m8n8.x4.trans.shared.b16 {%0,%1,%2,%3}, [%4];"
        : "=r"(r[0]), "=r"(r[1]), "=r"(r[2]), "=r"(r[3]) : "r"(addr) : "memory");
}
__device__ __forceinline__ void ldsm_x2t(u32* r, u32 addr) {
    asm volatile("ldmatrix.sync.aligned.m8n8.x2.trans.shared.b16 {%0,%1}, [%2];"
        : "=r"(r[0]), "=r"(r[1]) : "r"(addr) : "memory");
}
__device__ __forceinline__ void mma_fp16(float* d, const u32* a, const u32* b) {
    asm volatile("mma.sync.aligned.m16n8k16.row.col.f32.f16.f16.f32 "
        "{%0,%1,%2,%3}, {%4,%5,%6,%7}, {%8,%9}, {%0,%1,%2,%3};"
        : "+f"(d[0]), "+f"(d[1]), "+f"(d[2]), "+f"(d[3])
        : "r"(a[0]), "r"(a[1]), "r"(a[2]), "r"(a[3]), "r"(b[0]), "r"(b[1]));
}
__device__ __forceinline__ void cp8(u32 dst, const void* src) {
    asm volatile("cp.async.ca.shared.global [%0], [%1], 8;" :: "r"(dst), "l"(src) : "memory");
}
#define CP_COMMIT() asm volatile("cp.async.commit_group;" ::: "memory")
#define CP_WAIT1()  asm volatile("cp.async.wait_group 1;" ::: "memory")
#define CP_WAITALL() asm volatile("cp.async.wait_group 0;" ::: "memory")
#define BAR_SYNC(id, cnt) asm volatile("bar.sync %0, %1;" :: "r"(id), "r"(cnt) : "memory")
#define BAR_ARRIVE(id, cnt) asm volatile("bar.arrive %0, %1;" :: "r"(id), "r"(cnt) : "memory")

__device__ __forceinline__ u32 packh(float a, float b) {
    __half h0 = __float2half_rn(a), h1 = __float2half_rn(b);
    return (u32)__half_as_ushort(h0) | ((u32)__half_as_ushort(h1) << 16);
}

// ---------------- K1: temporal mean, smem-staged fully-coalesced ----------------
// CTA = (8 channels, batch): stream 100KB via cp.async (every sector once),
// then warp-per-channel column reduction from smem.
__global__ void __launch_bounds__(256)
k1_mean(const float* __restrict__ x) {
    extern __shared__ float s1[];
    u32 sb = smem_u32(s1);
    int cg = blockIdx.x, b = blockIdx.y;
    int tid = threadIdx.x;
    const float* xsrc = x + (size_t)(b * CIN + cg * 8) * 3200;

    // coalesced load: 12800 float2 (threads stride 8B)
#pragma unroll
    for (int k = 0; k < 50; ++k) {
        int f2 = tid + 256 * k;
        cp8(sb + (u32)(f2 * 8), xsrc + 2 * f2);
    }
    CP_COMMIT();
    CP_WAITALL();
    __syncthreads();

    int c = tid >> 5, j = tid & 31;
    if (j >= JJ) return;
    const float* col = s1 + c * 3200 + j;
    float a0 = 0.f, a1 = 0.f, a2 = 0.f, a3 = 0.f;
#pragma unroll 8
    for (int t = 0; t < TT; t += 4) {
        a0 += col[t * JJ];
        a1 += col[(t + 1) * JJ];
        a2 += col[(t + 2) * JJ];
        a3 += col[(t + 3) * JJ];
    }
    g_xt_mean[(b * CIN + cg * 8 + c) * JJ + j] = ((a0 + a1) + (a2 + a3)) * (1.0f / TT);
}

// ---------------- K2: per-batch attention (512 thr, 4-way j-split GEMV) ----------------
__global__ void __launch_bounds__(512)
k2_attn(const float* __restrict__ adj,
        const float* __restrict__ Wk, const float* __restrict__ bk,
        const float* __restrict__ Wq, const float* __restrict__ bq,
        const float* __restrict__ alphaPtr) {
    int b = blockIdx.x;
    int tid = threadIdx.x;  // 512
    __shared__ float xt[CIN * 26];
    __shared__ float skk[COUT * 26];
    __shared__ float sqq[COUT * 26];
    __shared__ float sdyn[JJ * 26];

    for (int i = tid; i < CIN * JJ; i += 512) {
        int c = i / JJ, j = i - c * JJ;
        xt[c * 26 + j] = g_xt_mean[b * CIN * JJ + i];
    }
    __syncthreads();
    {
        int o = tid >> 2, part = tid & 3;
        int j0 = part * 7;
        int nj = (part == 3) ? 4 : 7;
        const float4* wk4 = (const float4*)(Wk + o * CIN);
        const float4* wq4 = (const float4*)(Wq + o * CIN);
        float ak[7], aq[7];
#pragma unroll
        for (int jj = 0; jj < 7; ++jj) { ak[jj] = 0.f; aq[jj] = 0.f; }
#pragma unroll 4
        for (int c4 = 0; c4 < CIN / 4; ++c4) {
            float4 wk = wk4[c4], wq = wq4[c4];
            const float* x0 = &xt[(c4 * 4) * 26] + j0;
#pragma unroll
            for (int jj = 0; jj < 7; ++jj) {
                if (jj < nj) {
                    float v0 = x0[jj], v1 = x0[26 + jj], v2 = x0[52 + jj], v3 = x0[78 + jj];
                    float a = ak[jj], q = aq[jj];
                    a = fmaf(wk.x, v0, a); q = fmaf(wq.x, v0, q);
                    a = fmaf(wk.y, v1, a); q = fmaf(wq.y, v1, q);
                    a = fmaf(wk.z, v2, a); q = fmaf(wq.z, v2, q);
                    a = fmaf(wk.w, v3, a); q = fmaf(wq.w, v3, q);
                    ak[jj] = a; aq[jj] = q;
                }
            }
        }
        float bko = bk[o], bqo = bq[o];
#pragma unroll
        for (int jj = 0; jj < 7; ++jj)
            if (jj < nj) {
                skk[o * 26 + j0 + jj] = ak[jj] + bko;
                sqq[o * 26 + j0 + jj] = aq[jj] + bqo;
            }
    }
    __syncthreads();
    const float inv_scale = 0.08838834764831843f;  // 1/sqrt(128)
    for (int i = tid; i < JJ * JJ; i += 512) {
        int j = i / JJ, k = i - j * JJ;
        float acc = 0.f;
        for (int o = 0; o < COUT; o++) acc = fmaf(sqq[o * 26 + j], skk[o * 26 + k], acc);
        sdyn[j * 26 + k] = acc * inv_scale;
    }
    __syncthreads();
    if (tid < JJ) {
        int j = tid;
        float m = -1e30f;
#pragma unroll
        for (int k = 0; k < JJ; k++) m = fmaxf(m, sdyn[j * 26 + k]);
        float e[JJ]; float s = 0.f;
#pragma unroll
        for (int k = 0; k < JJ; k++) { e[k] = expf(sdyn[j * 26 + k] - m); s += e[k]; }
        float inv = 1.0f / s;
#pragma unroll
        for (int k = 0; k < JJ; k++) sdyn[j * 26 + k] = e[k] * inv;
    }
    __syncthreads();
    float alpha = alphaPtr[0];
    for (int i = tid; i < JJ * JJ; i += 512) {
        int j = i / JJ, k = i - j * JJ;
        float acc = 0.f;
#pragma unroll
        for (int m2 = 0; m2 < JJ; m2++) acc = fmaf(adj[j * JJ + m2], sdyn[m2 * 26 + k], acc);
        g_E[b * JJ * JJ + i] = adj[j * JJ + k] + alpha * acc;
    }
    if (tid < JJ) {
        int k = tid;
        float acc = 0.f;
#pragma unroll
        for (int j = 0; j < JJ; j++) acc += sdyn[j * 26 + k];
        g_csf[b * JJ + k] = 1.0f + alpha * acc;
    }
}

// raw chunk loader: 3200 cp8 (128 rows x 25), coalesced 8B
__device__ __forceinline__ void load_raw(u32 sbase, int buf, const float* __restrict__ xb,
                                         int ch, int ptid) {
#pragma unroll
    for (int i = 0; i < 13; ++i) {
        int flat = ptid + 256 * i;
        if (flat < 3200) {
            int c = flat / 25, w = flat - 25 * c;
            cp8(sbase + SM_RAW(buf) + (u32)((c * RAWP + w * 2) * 4),
                xb + (size_t)c * 3200 + ch * 50 + w * 2);
        }
    }
    CP_COMMIT();
}

// ---------------- K3 ----------------
__global__ void __launch_bounds__(512, 1)
k3_main(const float* __restrict__ x, const float* __restrict__ Ws,
        const float* __restrict__ bs, const float* __restrict__ gamma,
        const float* __restrict__ beta, const float* __restrict__ rmean,
        const float* __restrict__ rvar, float* __restrict__ out) {
    extern __shared__ char sm[];
    u32 sbase = smem_u32(sm);
    int tid = threadIdx.x;
    int b = blockIdx.y, slab = blockIdx.x;
    int t0slab = slab * TSLAB;

    bool is_prod = tid >= 256;
    int ptid = tid & 255;
    const float* xb = x + (size_t)b * 409600 + (size_t)t0slab * 25;

    // ---- producers: cp.async raw chunks 0,1 ----
    if (is_prod) {
        load_raw(sbase, 0, xb, 0, ptid);
        load_raw(sbase, 1, xb, 1, ptid);
    }

    // ---- staging (all 512 threads) ----
    float* csf = (float*)(sm + SM_CSF);
    if (tid < 32) csf[tid] = (tid < JJ) ? g_csf[b * JJ + tid] : 0.f;
    if (tid >= 32 && tid < 160) {
        int o = tid - 32;
        float inv = gamma[o] * rsqrtf(rvar[o] + 1e-5f);
        float sh = beta[o] - rmean[o] * inv;
        ((float4*)(sm + SM_SBN))[o] = make_float4(inv, sh, bs[o], 0.f);
    }
    {
        __half* eh = (__half*)(sm + SM_E16H);
        __half* el = (__half*)(sm + SM_E16L);
        for (int i = tid; i < 32 * XP; i += 512) {
            int j = i / XP, n = i - j * XP;
            float v = (j < JJ && n < JJ) ? g_E[b * 625 + j * 25 + n] : 0.f;
            __half h = __float2half_rn(v);
            eh[i] = h;
            el[i] = __float2half_rn(v - __half2float(h));
        }
    }
    {
        __half* ah = (__half*)(sm + SM_A_HI);
        __half* al = (__half*)(sm + SM_A_LO);
        for (int i = tid; i < COUT * CIN; i += 512) {
            int o = i >> 7, c = i & 127;
            float v = Ws[i];
            __half hb = __float2half_rn(v);
            ah[o * AP + c] = hb;
            al[o * AP + c] = __float2half_rn(v - __half2float(hb));
        }
    }
    __syncthreads();

    if (!is_prod) {
        // ===== CONSUMERS (warps 0..7): Ahi-resident pipelined GEMM + epilogue =====
        int warp = tid >> 5, lane = tid & 31;
        int o0 = warp * 16;
        int gid = lane >> 2, tig = lane & 3;
        u32 arow  = (u32)(o0 + (lane & 15));
        u32 acsel = (u32)((lane >> 4) * 8);
        u32 brow  = (u32)((lane & 7) + ((lane >> 3) & 1) * 8);
        u32 bcsel = (u32)((lane >> 4) * 8);
        u32 brow2 = (u32)(lane & 15);
        int o_a = o0 + gid, o_b = o_a + 8;
        float ck = csf[lane & 31];
        float* outb = out + (size_t)b * 409600;
        const float4* sbn = (const float4*)(sm + SM_SBN);

        u32 AbH = sbase + (u32)SM_A_HI + (arow * AP + acsel) * 2;
        u32 AbL = sbase + (u32)SM_A_LO + (arow * AP + acsel) * 2;

        u32 fahi[8][4];
#pragma unroll
        for (int kt = 0; kt < 8; ++kt) ldsm_x4(fahi[kt], AbH + (u32)(kt * 32));

        for (int ch = 0; ch < NCHUNK; ++ch) {
            int cbuf = ch & 1;
            BAR_SYNC(BAR_FULL(cbuf), 512);

            u32 BbH = sbase + (u32)SM_BH(cbuf);
            u32 BbL = sbase + (u32)SM_BL(cbuf);
            u32 BroH  = BbH + (brow * BP + bcsel) * 2;
            u32 BroL  = BbL + (brow * BP + bcsel) * 2;
            u32 Bro2H = BbH + (brow2 * BP + 48u) * 2;
            u32 Bro2L = BbL + (brow2 * BP + 48u) * 2;

            float acc[NTILES][4];
#pragma unroll
            for (int nt = 0; nt < NTILES; ++nt)
#pragma unroll
                for (int r = 0; r < 4; ++r) acc[nt][r] = 0.f;

            u32 bhi[2][14], blo[14], alo[4];
#define LDBHI(pb, kt) do {                                                  \
    u32 kb = (u32)((kt) * 16 * BP * 2);                                     \
    ldsm_x4t(&bhi[pb][0],  BroH + kb);                                      \
    ldsm_x4t(&bhi[pb][4],  BroH + kb + 32u);                                \
    ldsm_x4t(&bhi[pb][8],  BroH + kb + 64u);                                \
    ldsm_x2t(&bhi[pb][12], Bro2H + kb);                                     \
} while (0)
#define LDBLO(kt) do {                                                      \
    u32 kb = (u32)((kt) * 16 * BP * 2);                                     \
    ldsm_x4t(&blo[0],  BroL + kb);                                          \
    ldsm_x4t(&blo[4],  BroL + kb + 32u);                                    \
    ldsm_x4t(&blo[8],  BroL + kb + 64u);                                    \
    ldsm_x2t(&blo[12], Bro2L + kb);                                         \
} while (0)
            LDBHI(0, 0);
#pragma unroll
            for (int kt = 0; kt < 8; ++kt) {
                int pb = kt & 1;
                LDBLO(kt);
                ldsm_x4(alo, AbL + (u32)(kt * 32));
                mma_fp16(acc[0], fahi[kt], &bhi[pb][0]);
                mma_fp16(acc[1], fahi[kt], &bhi[pb][2]);
                mma_fp16(acc[2], fahi[kt], &bhi[pb][4]);
                mma_fp16(acc[3], fahi[kt], &bhi[pb][6]);
                mma_fp16(acc[4], fahi[kt], &bhi[pb][8]);
                mma_fp16(acc[5], fahi[kt], &bhi[pb][10]);
                mma_fp16(acc[6], fahi[kt], &bhi[pb][12]);
                if (kt < 7) LDBHI(pb ^ 1, kt + 1);
                mma_fp16(acc[0], alo, &bhi[pb][0]);
                mma_fp16(acc[1], alo, &bhi[pb][2]);
                mma_fp16(acc[2], alo, &bhi[pb][4]);
                mma_fp16(acc[3], alo, &bhi[pb][6]);
                mma_fp16(acc[4], alo, &bhi[pb][8]);
                mma_fp16(acc[5], alo, &bhi[pb][10]);
                mma_fp16(acc[6], alo, &bhi[pb][12]);
                mma_fp16(acc[0], fahi[kt], &blo[0]);
                mma_fp16(acc[1], fahi[kt], &blo[2]);
                mma_fp16(acc[2], fahi[kt], &blo[4]);
                mma_fp16(acc[3], fahi[kt], &blo[6]);
                mma_fp16(acc[4], fahi[kt], &blo[8]);
                mma_fp16(acc[5], fahi[kt], &blo[10]);
                mma_fp16(acc[6], fahi[kt], &blo[12]);
            }
#undef LDBHI
#undef LDBLO

            BAR_SYNC(BAR_CONS, 256);
            float* D = (float*)(sm + SM_BH(cbuf));
#pragma unroll
            for (int nt = 0; nt < NTILES; ++nt) {
                int n0 = nt * 8 + tig * 2;
                D[o_a * 56 + n0]     = acc[nt][0];
                D[o_a * 56 + n0 + 1] = acc[nt][1];
                D[o_b * 56 + n0]     = acc[nt][2];
                D[o_b * 56 + n0 + 1] = acc[nt][3];
            }
            BAR_SYNC(BAR_CONS, 256);

            int tch = t0slab + ch * CHT;
#pragma unroll
            for (int rr = 0; rr < 32; ++rr) {
                int idx = warp * 32 + rr;
                int o = idx >> 1, tl = idx & 1;
                float4 bn = sbn[o];
                if (lane < JJ) {
                    float v = D[o * 56 + tl * 26 + lane];
                    float pre = fmaf(bn.z, ck, v);
                    outb[(size_t)o * 3200 + (tch + tl) * 25 + lane] =
                        fmaxf(fmaf(pre, bn.x, bn.y), 0.f);
                }
            }
            BAR_ARRIVE(BAR_FREE(cbuf), 512);
        }
    } else {
        // ===== PRODUCERS (warps 8..15): cvt + mix-MMA =====
        int pw = (tid >> 5) - 8;
        int lane = tid & 31;
        int mbase = 32 * pw;
        u32 xrow  = (u32)(lane & 15);
        u32 xcsel = (u32)((lane >> 4) * 8);
        u32 erow  = (u32)((lane & 7) + ((lane >> 3) & 1) * 8);
        u32 ecsel = (u32)((lane >> 4) * 8);
        int r_cv = ptid, c_cv = r_cv >> 1, t_cv = r_cv & 1;

        for (int ch = 0; ch < NCHUNK; ++ch) {
            int buf = ch & 1;
            if (ch < NCHUNK - 2) { CP_WAIT1(); } else { CP_WAITALL(); }
            BAR_SYNC(BAR_PROD, 256);

            {
                const float* xr = (const float*)(sm + SM_RAW(buf)) + c_cv * RAWP + t_cv * 25;
#pragma unroll
                for (int s = 0; s < 4; ++s) {
                    u32 hi[4], lo[4];
#pragma unroll
                    for (int qq = 0; qq < 4; ++qq) {
                        int q = 4 * s + qq;
                        float f0 = (2 * q < 25) ? xr[2 * q] : 0.f;
                        float f1 = (2 * q + 1 < 25) ? xr[2 * q + 1] : 0.f;
                        __half h0 = __float2half_rn(f0), h1 = __float2half_rn(f1);
                        hi[qq] = (u32)__half_as_ushort(h0) | ((u32)__half_as_ushort(h1) << 16);
                        lo[qq] = packh(f0 - __half2float(h0), f1 - __half2float(h1));
                    }
                    *(uint4*)(sm + SM_X_HI + r_cv * 80 + s * 16) = make_uint4(hi[0], hi[1], hi[2], hi[3]);
                    *(uint4*)(sm + SM_X_LO + r_cv * 80 + s * 16) = make_uint4(lo[0], lo[1], lo[2], lo[3]);
                }
            }
            BAR_SYNC(BAR_PROD, 256);

            if (ch + 2 < NCHUNK) load_raw(sbase, buf, xb, ch + 2, ptid);

            if (ch >= 2) BAR_SYNC(BAR_FREE(buf), 512);

            char* bh = sm + SM_BH(buf);
            char* bl = sm + SM_BL(buf);
#pragma unroll
            for (int mt = 0; mt < 2; ++mt) {
                u32 ro = (u32)((mbase + mt * 16) + xrow);
                u32 xfH[2][4], xfL[2][4], ef[2][2][4];
                float accm[4][4];
#pragma unroll
                for (int nt = 0; nt < 4; ++nt)
#pragma unroll
                    for (int r = 0; r < 4; ++r) accm[nt][r] = 0.f;
#pragma unroll
                for (int kt = 0; kt < 2; ++kt) {
                    ldsm_x4(xfH[kt], sbase + (u32)SM_X_HI + (ro * XP + (u32)(kt * 16) + xcsel) * 2);
                    ldsm_x4(xfL[kt], sbase + (u32)SM_X_LO + (ro * XP + (u32)(kt * 16) + xcsel) * 2);
                }
#pragma unroll
                for (int kt = 0; kt < 2; ++kt)
#pragma unroll
                    for (int n2 = 0; n2 < 2; ++n2)
                        ldsm_x4t(ef[kt][n2], sbase + (u32)SM_E16H +
                                 (((u32)(kt * 16) + erow) * XP + (u32)(n2 * 16) + ecsel) * 2);
#pragma unroll
                for (int kt = 0; kt < 2; ++kt)
#pragma unroll
                    for (int n2 = 0; n2 < 2; ++n2) {
                        mma_fp16(accm[2 * n2],     xfH[kt], ef[kt][n2]);
                        mma_fp16(accm[2 * n2 + 1], xfH[kt], ef[kt][n2] + 2);
                        mma_fp16(accm[2 * n2],     xfL[kt], ef[kt][n2]);
                        mma_fp16(accm[2 * n2 + 1], xfL[kt], ef[kt][n2] + 2);
                    }
#pragma unroll
                for (int kt = 0; kt < 2; ++kt)
#pragma unroll
                    for (int n2 = 0; n2 < 2; ++n2)
                        ldsm_x4t(ef[kt][n2], sbase + (u32)SM_E16L +
                                 (((u32)(kt * 16) + erow) * XP + (u32)(n2 * 16) + ecsel) * 2);
#pragma unroll
                for (int kt = 0; kt < 2; ++kt)
#pragma unroll
                    for (int n2 = 0; n2 < 2; ++n2) {
                        mma_fp16(accm[2 * n2],     xfH[kt], ef[kt][n2]);
                        mma_fp16(accm[2 * n2 + 1], xfH[kt], ef[kt][n2] + 2);
                    }

#pragma unroll
                for (int nt = 0; nt < 4; ++nt) {
                    int n0 = nt * 8 + (lane & 3) * 2;
                    if (n0 < 26) {
                        int rA = mbase + mt * 16 + (lane >> 2);
                        int rB = rA + 8;
                        {
                            int cc = rA >> 1, tl = rA & 1;
                            u32 off = (u32)((cc * BP + tl * 26 + n0) * 2);
                            float a0 = accm[nt][0], a1 = accm[nt][1];
                            __half h0 = __float2half_rn(a0), h1 = __float2half_rn(a1);
                            *(u32*)(bh + off) = (u32)__half_as_ushort(h0) | ((u32)__half_as_ushort(h1) << 16);
                            *(u32*)(bl + off) = packh(a0 - __half2float(h0), a1 - __half2float(h1));
                        }
                        {
                            int cc = rB >> 1, tl = rB & 1;
                            u32 off = (u32)((cc * BP + tl * 26 + n0) * 2);
                            float a0 = accm[nt][2], a1 = accm[nt][3];
                            __half h0 = __float2half_rn(a0), h1 = __float2half_rn(a1);
                            *(u32*)(bh + off) = (u32)__half_as_ushort(h0) | ((u32)__half_as_ushort(h1) << 16);
                            *(u32*)(bl + off) = packh(a0 - __half2float(h0), a1 - __half2float(h1));
                        }
                    }
                }
            }
            BAR_ARRIVE(BAR_FULL(buf), 512);
        }
    }
}

// ---------------- launch ----------------
extern "C" void kernel_launch(void* const* d_in, const int* in_sizes, int n_in,
                              void* d_out, int out_size) {
    const float* x     = (const float*)d_in[0];
    const float* adj   = (const float*)d_in[1];
    const float* Wk    = (const float*)d_in[2];
    const float* bk    = (const float*)d_in[3];
    const float* Wq    = (const float*)d_in[4];
    const float* bq    = (const float*)d_in[5];
    const float* Ws    = (const float*)d_in[6];
    const float* bs    = (const float*)d_in[7];
    const float* gamma = (const float*)d_in[8];
    const float* beta  = (const float*)d_in[9];
    const float* rmean = (const float*)d_in[10];
    const float* rvar  = (const float*)d_in[11];
    const float* alpha = (const float*)d_in[12];
    float* out = (float*)d_out;

    cudaFuncSetAttribute(k1_mean, cudaFuncAttributeMaxDynamicSharedMemorySize, K1_SMEM);
    cudaFuncSetAttribute(k3_main, cudaFuncAttributeMaxDynamicSharedMemorySize, SMEM_TOTAL);

    k1_mean<<<dim3(16, NB), 256, K1_SMEM>>>(x);
    k2_attn<<<NB, 512>>>(adj, Wk, bk, Wq, bq, alpha);
    k3_main<<<dim3(TT / TSLAB, NB), 512, SMEM_TOTAL>>>(x, Ws, bs, gamma, beta, rmean, rvar, out);
}